// round 2
// baseline (speedup 1.0000x reference)
#include <cuda_runtime.h>

#define N_NODES 100000
#define N_EDGES 1600000
#define DF      128
#define TS      68   // padded smem row stride (floats)

// ---------------- scratch (device globals: allocation-free) ----------------
static __device__ float g_k[(size_t)N_NODES * DF];
static __device__ float g_q[(size_t)N_NODES * DF];
static __device__ float g_v[(size_t)N_NODES * DF];
static __device__ float g_s[(size_t)N_NODES * DF];
static __device__ float g_h0[(size_t)N_NODES * DF];
static __device__ float g_h1[(size_t)N_NODES * DF];
static __device__ int   g_rowptr[N_NODES + 1];
static __device__ int   g_fill[N_NODES];
static __device__ int   g_esrc[N_EDGES];

// ---------------- CSR build ----------------
__global__ void zero_cnt_kernel() {
    int i = blockIdx.x * blockDim.x + threadIdx.x;
    if (i < N_NODES) g_fill[i] = 0;
}

__global__ void hist_kernel(const int* __restrict__ dst) {
    int e = blockIdx.x * blockDim.x + threadIdx.x;
    if (e < N_EDGES) atomicAdd(&g_fill[dst[e]], 1);
}

// single-block exclusive scan of g_fill -> g_rowptr (and reset g_fill = rowptr)
__global__ void scan_kernel() {
    __shared__ int wsum[32];
    __shared__ int carry;
    int tid = threadIdx.x, lane = tid & 31, wid = tid >> 5;
    if (tid == 0) carry = 0;
    __syncthreads();
    for (int base = 0; base < N_NODES; base += 1024) {
        int idx = base + tid;
        int v = (idx < N_NODES) ? g_fill[idx] : 0;
        int x = v;
#pragma unroll
        for (int o = 1; o < 32; o <<= 1) {
            int t = __shfl_up_sync(0xffffffffu, x, o);
            if (lane >= o) x += t;
        }
        if (lane == 31) wsum[wid] = x;
        __syncthreads();
        if (wid == 0) {
            int y = wsum[lane];
#pragma unroll
            for (int o = 1; o < 32; o <<= 1) {
                int t = __shfl_up_sync(0xffffffffu, y, o);
                if (lane >= o) y += t;
            }
            wsum[lane] = y;
        }
        __syncthreads();
        int excl = carry + (x - v) + (wid ? wsum[wid - 1] : 0);
        if (idx < N_NODES) { g_rowptr[idx] = excl; g_fill[idx] = excl; }
        __syncthreads();
        if (tid == 0) carry += wsum[31];
        __syncthreads();
    }
    if (tid == 0) g_rowptr[N_NODES] = N_EDGES;
}

__global__ void scatter_kernel(const int* __restrict__ src, const int* __restrict__ dst) {
    int e = blockIdx.x * blockDim.x + threadIdx.x;
    if (e < N_EDGES) {
        int d = dst[e];
        int p = atomicAdd(&g_fill[d], 1);
        g_esrc[p] = src[e];
    }
}

// ---------------- fused 4-way GEMM: {k,q,v,s} = X @ {Wk,Wq,Wv,Ws} (+bias on s) ----
// grid = (8 column-tiles, 1563 row-tiles), 256 threads, 64x64 tile, K=128 resident.
__global__ void __launch_bounds__(256) gemm4_kernel(
    const float* __restrict__ Xext, int xsel,
    const float* __restrict__ Wk, const float* __restrict__ Wq,
    const float* __restrict__ Wv, const float* __restrict__ Ws,
    const float* __restrict__ bias)
{
    extern __shared__ float sm[];
    float* As = sm;             // [128][TS] transposed X tile: As[k][m]
    float* Bs = sm + 128 * TS;  // [128][TS] W tile:            Bs[k][n]

    const float* X = xsel ? g_h0 : Xext;

    int tid = threadIdx.x;
    int tx = tid & 15, ty = tid >> 4;
    int c = blockIdx.x;                 // 0..7 column tile
    int row0 = blockIdx.y * 64;
    int mat = c >> 1;
    int off = (c & 1) * 64;
    const float* W  = (mat == 0) ? Wk : (mat == 1) ? Wq : (mat == 2) ? Wv : Ws;
    float*       Out = (mat == 0) ? g_k : (mat == 1) ? g_q : (mat == 2) ? g_v : g_s;

    // load X tile (64 rows x 128 cols) transposed into As
#pragma unroll
    for (int p = 0; p < 8; p++) {
        int f = tid + p * 256;          // 0..2047
        int r  = f >> 5;                // 0..63
        int kq = (f & 31) << 2;         // 0..124
        int gr = row0 + r;
        float4 xv = make_float4(0.f, 0.f, 0.f, 0.f);
        if (gr < N_NODES)
            xv = *reinterpret_cast<const float4*>(X + (size_t)gr * DF + kq);
        As[(kq + 0) * TS + r] = xv.x;
        As[(kq + 1) * TS + r] = xv.y;
        As[(kq + 2) * TS + r] = xv.z;
        As[(kq + 3) * TS + r] = xv.w;
    }
    // load W tile (128 rows x 64 cols)
#pragma unroll
    for (int p = 0; p < 8; p++) {
        int f = tid + p * 256;
        int kk = f >> 4;                // 0..127
        int nq = (f & 15) << 2;         // 0..60
        float4 wv = *reinterpret_cast<const float4*>(W + (size_t)kk * DF + off + nq);
        *reinterpret_cast<float4*>(&Bs[kk * TS + nq]) = wv;
    }
    __syncthreads();

    unsigned long long acc[4][2];
#pragma unroll
    for (int i = 0; i < 4; i++) { acc[i][0] = 0ull; acc[i][1] = 0ull; }

    int ty4 = ty * 4, tx4 = tx * 4;
#pragma unroll 8
    for (int k = 0; k < 128; k++) {
        float4 a = *reinterpret_cast<const float4*>(&As[k * TS + ty4]);
        float4 b = *reinterpret_cast<const float4*>(&Bs[k * TS + tx4]);
        unsigned long long b01, b23;
        asm("mov.b64 %0,{%1,%2};" : "=l"(b01)
            : "r"(__float_as_uint(b.x)), "r"(__float_as_uint(b.y)));
        asm("mov.b64 %0,{%1,%2};" : "=l"(b23)
            : "r"(__float_as_uint(b.z)), "r"(__float_as_uint(b.w)));
        float av[4] = {a.x, a.y, a.z, a.w};
#pragma unroll
        for (int i = 0; i < 4; i++) {
            unsigned long long aii;
            asm("mov.b64 %0,{%1,%1};" : "=l"(aii) : "r"(__float_as_uint(av[i])));
            asm("fma.rn.f32x2 %0,%1,%2,%0;" : "+l"(acc[i][0]) : "l"(aii), "l"(b01));
            asm("fma.rn.f32x2 %0,%1,%2,%0;" : "+l"(acc[i][1]) : "l"(aii), "l"(b23));
        }
    }

    float4 bb = make_float4(0.f, 0.f, 0.f, 0.f);
    if (mat == 3) bb = *reinterpret_cast<const float4*>(bias + off + tx4);
#pragma unroll
    for (int i = 0; i < 4; i++) {
        int gr = row0 + ty4 + i;
        if (gr < N_NODES) {
            float2 p0 = *reinterpret_cast<float2*>(&acc[i][0]);
            float2 p1 = *reinterpret_cast<float2*>(&acc[i][1]);
            float4 r = make_float4(p0.x + bb.x, p0.y + bb.y, p1.x + bb.z, p1.y + bb.w);
            *reinterpret_cast<float4*>(Out + (size_t)gr * DF + off + tx4) = r;
        }
    }
}

// ---------------- edge aggregation: one warp per destination node ----------------
__global__ void agg_kernel(int osel, int do_relu) {
    int gw = (blockIdx.x * blockDim.x + threadIdx.x) >> 5;
    if (gw >= N_NODES) return;
    int lane = threadIdx.x & 31;
    float* out = osel ? g_h1 : g_h0;

    size_t fo = (size_t)gw * DF + lane * 4;
    float4 kk = *reinterpret_cast<const float4*>(g_k + fo);
    float4 acc = make_float4(0.f, 0.f, 0.f, 0.f);

    int beg = g_rowptr[gw], end = g_rowptr[gw + 1];
    for (int j = beg; j < end; j++) {
        int s = g_esrc[j];
        size_t so = (size_t)s * DF + lane * 4;
        float4 qq = *reinterpret_cast<const float4*>(g_q + so);
        float4 vv = *reinterpret_cast<const float4*>(g_v + so);
        acc.x += __fdividef(vv.x, 1.f + __expf(-(kk.x + qq.x)));
        acc.y += __fdividef(vv.y, 1.f + __expf(-(kk.y + qq.y)));
        acc.z += __fdividef(vv.z, 1.f + __expf(-(kk.z + qq.z)));
        acc.w += __fdividef(vv.w, 1.f + __expf(-(kk.w + qq.w)));
    }
    float4 ss = *reinterpret_cast<const float4*>(g_s + fo);
    float4 r = make_float4(acc.x + ss.x, acc.y + ss.y, acc.z + ss.z, acc.w + ss.w);
    if (do_relu) {
        r.x = fmaxf(r.x, 0.f); r.y = fmaxf(r.y, 0.f);
        r.z = fmaxf(r.z, 0.f); r.w = fmaxf(r.w, 0.f);
    }
    *reinterpret_cast<float4*>(out + fo) = r;
}

// ---------------- layer 3 (D_OUT = 1) ----------------
__global__ void gemm3_kernel(const float* __restrict__ Wk, const float* __restrict__ Wq,
                             const float* __restrict__ Wv, const float* __restrict__ Ws,
                             const float* __restrict__ bias)
{
    int gw = (blockIdx.x * blockDim.x + threadIdx.x) >> 5;
    if (gw >= N_NODES) return;
    int lane = threadIdx.x & 31;
    float4 x4 = *reinterpret_cast<const float4*>(g_h1 + (size_t)gw * DF + lane * 4);
    float4 wk = *reinterpret_cast<const float4*>(Wk + lane * 4);
    float4 wq = *reinterpret_cast<const float4*>(Wq + lane * 4);
    float4 wv = *reinterpret_cast<const float4*>(Wv + lane * 4);
    float4 ws = *reinterpret_cast<const float4*>(Ws + lane * 4);
    float pk = x4.x * wk.x + x4.y * wk.y + x4.z * wk.z + x4.w * wk.w;
    float pq = x4.x * wq.x + x4.y * wq.y + x4.z * wq.z + x4.w * wq.w;
    float pv = x4.x * wv.x + x4.y * wv.y + x4.z * wv.z + x4.w * wv.w;
    float ps = x4.x * ws.x + x4.y * ws.y + x4.z * ws.z + x4.w * ws.w;
#pragma unroll
    for (int o = 16; o; o >>= 1) {
        pk += __shfl_xor_sync(0xffffffffu, pk, o);
        pq += __shfl_xor_sync(0xffffffffu, pq, o);
        pv += __shfl_xor_sync(0xffffffffu, pv, o);
        ps += __shfl_xor_sync(0xffffffffu, ps, o);
    }
    if (lane == 0) {
        g_k[gw] = pk; g_q[gw] = pq; g_v[gw] = pv; g_s[gw] = ps + bias[0];
    }
}

__global__ void agg3_kernel(float* __restrict__ out) {
    int i = blockIdx.x * blockDim.x + threadIdx.x;
    if (i >= N_NODES) return;
    float ki = g_k[i];
    float acc = 0.f;
    int end = g_rowptr[i + 1];
    for (int j = g_rowptr[i]; j < end; j++) {
        int s = g_esrc[j];
        acc += __fdividef(g_v[s], 1.f + __expf(-(ki + g_q[s])));
    }
    out[i] = acc + g_s[i];
}

// ---------------- launch ----------------
extern "C" void kernel_launch(void* const* d_in, const int* in_sizes, int n_in,
                              void* d_out, int out_size) {
    const float* x   = (const float*)d_in[0];
    const int*   ei  = (const int*)d_in[1];
    const int*   src = ei;
    const int*   dst = ei + N_EDGES;
    const float* Wk1 = (const float*)d_in[2];
    const float* Wq1 = (const float*)d_in[3];
    const float* Wv1 = (const float*)d_in[4];
    const float* Ws1 = (const float*)d_in[5];
    const float* b1  = (const float*)d_in[6];
    const float* Wk2 = (const float*)d_in[7];
    const float* Wq2 = (const float*)d_in[8];
    const float* Wv2 = (const float*)d_in[9];
    const float* Ws2 = (const float*)d_in[10];
    const float* b2  = (const float*)d_in[11];
    const float* Wk3 = (const float*)d_in[12];
    const float* Wq3 = (const float*)d_in[13];
    const float* Wv3 = (const float*)d_in[14];
    const float* Ws3 = (const float*)d_in[15];
    const float* b3  = (const float*)d_in[16];
    float* out = (float*)d_out;

    const int smem = 2 * 128 * TS * sizeof(float);  // 69632
    cudaFuncSetAttribute(gemm4_kernel, cudaFuncAttributeMaxDynamicSharedMemorySize, smem);

    // CSR build (reused by all 3 layers)
    zero_cnt_kernel<<<(N_NODES + 255) / 256, 256>>>();
    hist_kernel<<<(N_EDGES + 255) / 256, 256>>>(dst);
    scan_kernel<<<1, 1024>>>();
    scatter_kernel<<<(N_EDGES + 255) / 256, 256>>>(src, dst);

    dim3 ggrid(8, (N_NODES + 63) / 64);
    int  agg_blocks = (N_NODES * 32 + 255) / 256;

    // layer 1
    gemm4_kernel<<<ggrid, 256, smem>>>(x, 0, Wk1, Wq1, Wv1, Ws1, b1);
    agg_kernel<<<agg_blocks, 256>>>(0, 1);
    // layer 2
    gemm4_kernel<<<ggrid, 256, smem>>>(nullptr, 1, Wk2, Wq2, Wv2, Ws2, b2);
    agg_kernel<<<agg_blocks, 256>>>(1, 1);
    // layer 3
    gemm3_kernel<<<agg_blocks, 256>>>(Wk3, Wq3, Wv3, Ws3, b3);
    agg3_kernel<<<(N_NODES + 255) / 256, 256>>>(out);
}

// round 3
// speedup vs baseline: 1.0031x; 1.0031x over previous
#include <cuda_runtime.h>

#define N_NODES 100000
#define N_EDGES 1600000
#define DF      128
#define TS      68   // padded smem row stride (floats)

// ---------------- scratch (device globals: allocation-free) ----------------
static __device__ float g_k[(size_t)N_NODES * DF];
static __device__ float g_q[(size_t)N_NODES * DF];
static __device__ float g_v[(size_t)N_NODES * DF];
static __device__ float g_s[(size_t)N_NODES * DF];
static __device__ float g_h0[(size_t)N_NODES * DF];
static __device__ float g_h1[(size_t)N_NODES * DF];
static __device__ int   g_rowptr[N_NODES + 1];
static __device__ int   g_fill[N_NODES];
static __device__ int   g_esrc[N_EDGES];

// ---------------- CSR build ----------------
__global__ void zero_cnt_kernel() {
    int i = blockIdx.x * blockDim.x + threadIdx.x;
    if (i < N_NODES) g_fill[i] = 0;
}

__global__ void hist_kernel(const int* __restrict__ dst) {
    int e = blockIdx.x * blockDim.x + threadIdx.x;
    if (e < N_EDGES) atomicAdd(&g_fill[dst[e]], 1);
}

// single-block exclusive scan of g_fill -> g_rowptr (and reset g_fill = rowptr)
__global__ void scan_kernel() {
    __shared__ int wsum[32];
    __shared__ int carry;
    int tid = threadIdx.x, lane = tid & 31, wid = tid >> 5;
    if (tid == 0) carry = 0;
    __syncthreads();
    for (int base = 0; base < N_NODES; base += 1024) {
        int idx = base + tid;
        int v = (idx < N_NODES) ? g_fill[idx] : 0;
        int x = v;
#pragma unroll
        for (int o = 1; o < 32; o <<= 1) {
            int t = __shfl_up_sync(0xffffffffu, x, o);
            if (lane >= o) x += t;
        }
        if (lane == 31) wsum[wid] = x;
        __syncthreads();
        if (wid == 0) {
            int y = wsum[lane];
#pragma unroll
            for (int o = 1; o < 32; o <<= 1) {
                int t = __shfl_up_sync(0xffffffffu, y, o);
                if (lane >= o) y += t;
            }
            wsum[lane] = y;
        }
        __syncthreads();
        int excl = carry + (x - v) + (wid ? wsum[wid - 1] : 0);
        if (idx < N_NODES) { g_rowptr[idx] = excl; g_fill[idx] = excl; }
        __syncthreads();
        if (tid == 0) carry += wsum[31];
        __syncthreads();
    }
    if (tid == 0) g_rowptr[N_NODES] = N_EDGES;
}

__global__ void scatter_kernel(const int* __restrict__ src, const int* __restrict__ dst) {
    int e = blockIdx.x * blockDim.x + threadIdx.x;
    if (e < N_EDGES) {
        int d = dst[e];
        int p = atomicAdd(&g_fill[d], 1);
        g_esrc[p] = src[e];
    }
}

// ---------------- fused 4-way GEMM: {k,q,v,s} = X @ {Wk,Wq,Wv,Ws} (+bias on s) ----
// grid = (8 column-tiles, 1563 row-tiles), 256 threads, 64x64 tile, K=128 resident.
__global__ void __launch_bounds__(256) gemm4_kernel(
    const float* __restrict__ Xext, int xsel,
    const float* __restrict__ Wk, const float* __restrict__ Wq,
    const float* __restrict__ Wv, const float* __restrict__ Ws,
    const float* __restrict__ bias)
{
    extern __shared__ float sm[];
    float* As = sm;             // [128][TS] transposed X tile: As[k][m]
    float* Bs = sm + 128 * TS;  // [128][TS] W tile:            Bs[k][n]

    const float* X = xsel ? g_h0 : Xext;

    int tid = threadIdx.x;
    int tx = tid & 15, ty = tid >> 4;
    int c = blockIdx.x;                 // 0..7 column tile
    int row0 = blockIdx.y * 64;
    int mat = c >> 1;
    int off = (c & 1) * 64;
    const float* W  = (mat == 0) ? Wk : (mat == 1) ? Wq : (mat == 2) ? Wv : Ws;
    float*       Out = (mat == 0) ? g_k : (mat == 1) ? g_q : (mat == 2) ? g_v : g_s;

    // load X tile (64 rows x 128 cols) transposed into As
#pragma unroll
    for (int p = 0; p < 8; p++) {
        int f = tid + p * 256;          // 0..2047
        int r  = f >> 5;                // 0..63
        int kq = (f & 31) << 2;         // 0..124
        int gr = row0 + r;
        float4 xv = make_float4(0.f, 0.f, 0.f, 0.f);
        if (gr < N_NODES)
            xv = *reinterpret_cast<const float4*>(X + (size_t)gr * DF + kq);
        As[(kq + 0) * TS + r] = xv.x;
        As[(kq + 1) * TS + r] = xv.y;
        As[(kq + 2) * TS + r] = xv.z;
        As[(kq + 3) * TS + r] = xv.w;
    }
    // load W tile (128 rows x 64 cols)
#pragma unroll
    for (int p = 0; p < 8; p++) {
        int f = tid + p * 256;
        int kk = f >> 4;                // 0..127
        int nq = (f & 15) << 2;         // 0..60
        float4 wv = *reinterpret_cast<const float4*>(W + (size_t)kk * DF + off + nq);
        *reinterpret_cast<float4*>(&Bs[kk * TS + nq]) = wv;
    }
    __syncthreads();

    unsigned long long acc[4][2];
#pragma unroll
    for (int i = 0; i < 4; i++) { acc[i][0] = 0ull; acc[i][1] = 0ull; }

    int ty4 = ty * 4, tx4 = tx * 4;
#pragma unroll 8
    for (int k = 0; k < 128; k++) {
        float4 a = *reinterpret_cast<const float4*>(&As[k * TS + ty4]);
        float4 b = *reinterpret_cast<const float4*>(&Bs[k * TS + tx4]);
        unsigned long long b01, b23;
        asm("mov.b64 %0,{%1,%2};" : "=l"(b01)
            : "r"(__float_as_uint(b.x)), "r"(__float_as_uint(b.y)));
        asm("mov.b64 %0,{%1,%2};" : "=l"(b23)
            : "r"(__float_as_uint(b.z)), "r"(__float_as_uint(b.w)));
        float av[4] = {a.x, a.y, a.z, a.w};
#pragma unroll
        for (int i = 0; i < 4; i++) {
            unsigned long long aii;
            asm("mov.b64 %0,{%1,%1};" : "=l"(aii) : "r"(__float_as_uint(av[i])));
            asm("fma.rn.f32x2 %0,%1,%2,%0;" : "+l"(acc[i][0]) : "l"(aii), "l"(b01));
            asm("fma.rn.f32x2 %0,%1,%2,%0;" : "+l"(acc[i][1]) : "l"(aii), "l"(b23));
        }
    }

    float4 bb = make_float4(0.f, 0.f, 0.f, 0.f);
    if (mat == 3) bb = *reinterpret_cast<const float4*>(bias + off + tx4);
#pragma unroll
    for (int i = 0; i < 4; i++) {
        int gr = row0 + ty4 + i;
        if (gr < N_NODES) {
            float2 p0 = *reinterpret_cast<float2*>(&acc[i][0]);
            float2 p1 = *reinterpret_cast<float2*>(&acc[i][1]);
            float4 r = make_float4(p0.x + bb.x, p0.y + bb.y, p1.x + bb.z, p1.y + bb.w);
            *reinterpret_cast<float4*>(Out + (size_t)gr * DF + off + tx4) = r;
        }
    }
}

// ---------------- edge aggregation: one warp per destination node ----------------
__global__ void agg_kernel(int osel, int do_relu) {
    int gw = (blockIdx.x * blockDim.x + threadIdx.x) >> 5;
    if (gw >= N_NODES) return;
    int lane = threadIdx.x & 31;
    float* out = osel ? g_h1 : g_h0;

    size_t fo = (size_t)gw * DF + lane * 4;
    float4 kk = *reinterpret_cast<const float4*>(g_k + fo);
    float4 acc = make_float4(0.f, 0.f, 0.f, 0.f);

    int beg = g_rowptr[gw], end = g_rowptr[gw + 1];
    for (int j = beg; j < end; j++) {
        int s = g_esrc[j];
        size_t so = (size_t)s * DF + lane * 4;
        float4 qq = *reinterpret_cast<const float4*>(g_q + so);
        float4 vv = *reinterpret_cast<const float4*>(g_v + so);
        acc.x += __fdividef(vv.x, 1.f + __expf(-(kk.x + qq.x)));
        acc.y += __fdividef(vv.y, 1.f + __expf(-(kk.y + qq.y)));
        acc.z += __fdividef(vv.z, 1.f + __expf(-(kk.z + qq.z)));
        acc.w += __fdividef(vv.w, 1.f + __expf(-(kk.w + qq.w)));
    }
    float4 ss = *reinterpret_cast<const float4*>(g_s + fo);
    float4 r = make_float4(acc.x + ss.x, acc.y + ss.y, acc.z + ss.z, acc.w + ss.w);
    if (do_relu) {
        r.x = fmaxf(r.x, 0.f); r.y = fmaxf(r.y, 0.f);
        r.z = fmaxf(r.z, 0.f); r.w = fmaxf(r.w, 0.f);
    }
    *reinterpret_cast<float4*>(out + fo) = r;
}

// ---------------- layer 3 (D_OUT = 1) ----------------
__global__ void gemm3_kernel(const float* __restrict__ Wk, const float* __restrict__ Wq,
                             const float* __restrict__ Wv, const float* __restrict__ Ws,
                             const float* __restrict__ bias)
{
    int gw = (blockIdx.x * blockDim.x + threadIdx.x) >> 5;
    if (gw >= N_NODES) return;
    int lane = threadIdx.x & 31;
    float4 x4 = *reinterpret_cast<const float4*>(g_h1 + (size_t)gw * DF + lane * 4);
    float4 wk = *reinterpret_cast<const float4*>(Wk + lane * 4);
    float4 wq = *reinterpret_cast<const float4*>(Wq + lane * 4);
    float4 wv = *reinterpret_cast<const float4*>(Wv + lane * 4);
    float4 ws = *reinterpret_cast<const float4*>(Ws + lane * 4);
    float pk = x4.x * wk.x + x4.y * wk.y + x4.z * wk.z + x4.w * wk.w;
    float pq = x4.x * wq.x + x4.y * wq.y + x4.z * wq.z + x4.w * wq.w;
    float pv = x4.x * wv.x + x4.y * wv.y + x4.z * wv.z + x4.w * wv.w;
    float ps = x4.x * ws.x + x4.y * ws.y + x4.z * ws.z + x4.w * ws.w;
#pragma unroll
    for (int o = 16; o; o >>= 1) {
        pk += __shfl_xor_sync(0xffffffffu, pk, o);
        pq += __shfl_xor_sync(0xffffffffu, pq, o);
        pv += __shfl_xor_sync(0xffffffffu, pv, o);
        ps += __shfl_xor_sync(0xffffffffu, ps, o);
    }
    if (lane == 0) {
        g_k[gw] = pk; g_q[gw] = pq; g_v[gw] = pv; g_s[gw] = ps + bias[0];
    }
}

__global__ void agg3_kernel(float* __restrict__ out) {
    int i = blockIdx.x * blockDim.x + threadIdx.x;
    if (i >= N_NODES) return;
    float ki = g_k[i];
    float acc = 0.f;
    int end = g_rowptr[i + 1];
    for (int j = g_rowptr[i]; j < end; j++) {
        int s = g_esrc[j];
        acc += __fdividef(g_v[s], 1.f + __expf(-(ki + g_q[s])));
    }
    out[i] = acc + g_s[i];
}

// ---------------- launch ----------------
extern "C" void kernel_launch(void* const* d_in, const int* in_sizes, int n_in,
                              void* d_out, int out_size) {
    const float* x   = (const float*)d_in[0];
    const int*   ei  = (const int*)d_in[1];
    const int*   src = ei;
    const int*   dst = ei + N_EDGES;
    const float* Wk1 = (const float*)d_in[2];
    const float* Wq1 = (const float*)d_in[3];
    const float* Wv1 = (const float*)d_in[4];
    const float* Ws1 = (const float*)d_in[5];
    const float* b1  = (const float*)d_in[6];
    const float* Wk2 = (const float*)d_in[7];
    const float* Wq2 = (const float*)d_in[8];
    const float* Wv2 = (const float*)d_in[9];
    const float* Ws2 = (const float*)d_in[10];
    const float* b2  = (const float*)d_in[11];
    const float* Wk3 = (const float*)d_in[12];
    const float* Wq3 = (const float*)d_in[13];
    const float* Wv3 = (const float*)d_in[14];
    const float* Ws3 = (const float*)d_in[15];
    const float* b3  = (const float*)d_in[16];
    float* out = (float*)d_out;

    const int smem = 2 * 128 * TS * sizeof(float);  // 69632
    cudaFuncSetAttribute(gemm4_kernel, cudaFuncAttributeMaxDynamicSharedMemorySize, smem);

    // CSR build (reused by all 3 layers)
    zero_cnt_kernel<<<(N_NODES + 255) / 256, 256>>>();
    hist_kernel<<<(N_EDGES + 255) / 256, 256>>>(dst);
    scan_kernel<<<1, 1024>>>();
    scatter_kernel<<<(N_EDGES + 255) / 256, 256>>>(src, dst);

    dim3 ggrid(8, (N_NODES + 63) / 64);
    int  agg_blocks = (N_NODES * 32 + 255) / 256;

    // layer 1
    gemm4_kernel<<<ggrid, 256, smem>>>(x, 0, Wk1, Wq1, Wv1, Ws1, b1);
    agg_kernel<<<agg_blocks, 256>>>(0, 1);
    // layer 2
    gemm4_kernel<<<ggrid, 256, smem>>>(nullptr, 1, Wk2, Wq2, Wv2, Ws2, b2);
    agg_kernel<<<agg_blocks, 256>>>(1, 1);
    // layer 3
    gemm3_kernel<<<agg_blocks, 256>>>(Wk3, Wq3, Wv3, Ws3, b3);
    agg3_kernel<<<(N_NODES + 255) / 256, 256>>>(out);
}

// round 6
// speedup vs baseline: 1.7340x; 1.7286x over previous
#include <cuda_runtime.h>
#include <cuda_bf16.h>
#include <cstdint>

#define N_NODES 100000
#define N_EDGES 1600000
#define DF      128
#define NTILES  782          // ceil(100000/128)

// ---------------- scratch (device globals: allocation-free) ----------------
static __device__ float g_k[(size_t)N_NODES * DF];
static __device__ float g_q[(size_t)N_NODES * DF];
static __device__ float g_v[(size_t)N_NODES * DF];
static __device__ float g_s[(size_t)N_NODES * DF];
static __device__ float g_h0[(size_t)N_NODES * DF];
static __device__ float g_h1[(size_t)N_NODES * DF];
static __device__ int   g_rowptr[N_NODES + 1];
static __device__ int   g_fill[N_NODES];
static __device__ int   g_esrc[N_EDGES];
// bf16 hi/lo split operands
static __device__ __nv_bfloat16 g_ahi[(size_t)N_NODES * DF];
static __device__ __nv_bfloat16 g_alo[(size_t)N_NODES * DF];
static __device__ __nv_bfloat16 g_bthi[4 * 128 * 128];   // transposed [mat][n][k]
static __device__ __nv_bfloat16 g_btlo[4 * 128 * 128];

// ---------------- helpers ----------------
__device__ __forceinline__ uint32_t smem_u32(const void* p) {
    uint32_t a;
    asm("{ .reg .u64 t; cvta.to.shared.u64 t, %1; cvt.u32.u64 %0, t; }" : "=r"(a) : "l"(p));
    return a;
}

// XOR swizzle: tile is [128 rows][128 bf16] = row stride 256B, 16 chunks of 16B.
__device__ __forceinline__ uint32_t swz(int row, int chunk) {
    return (uint32_t)(row * 256 + ((chunk ^ (row & 7)) << 4));
}

#define LDSM_X4(r0, r1, r2, r3, addr) \
    asm volatile("ldmatrix.sync.aligned.m8n8.x4.shared.b16 {%0,%1,%2,%3}, [%4];" \
        : "=r"(r0), "=r"(r1), "=r"(r2), "=r"(r3) : "r"(addr))
#define LDSM_X2(r0, r1, addr) \
    asm volatile("ldmatrix.sync.aligned.m8n8.x2.shared.b16 {%0,%1}, [%2];" \
        : "=r"(r0), "=r"(r1) : "r"(addr))
#define MMA16816(d, a, b) \
    asm volatile("mma.sync.aligned.m16n8k16.row.col.f32.bf16.bf16.f32 " \
        "{%0,%1,%2,%3},{%4,%5,%6,%7},{%8,%9},{%0,%1,%2,%3};" \
        : "+f"((d)[0]), "+f"((d)[1]), "+f"((d)[2]), "+f"((d)[3]) \
        : "r"((a)[0]), "r"((a)[1]), "r"((a)[2]), "r"((a)[3]), "r"((b)[0]), "r"((b)[1]))

// ---------------- CSR build ----------------
__global__ void zero_cnt_kernel() {
    int i = blockIdx.x * blockDim.x + threadIdx.x;
    if (i < N_NODES) g_fill[i] = 0;
}
__global__ void hist_kernel(const int* __restrict__ dst) {
    int e = blockIdx.x * blockDim.x + threadIdx.x;
    if (e < N_EDGES) atomicAdd(&g_fill[dst[e]], 1);
}
__global__ void scan_kernel() {
    __shared__ int wsum[32];
    __shared__ int carry;
    int tid = threadIdx.x, lane = tid & 31, wid = tid >> 5;
    if (tid == 0) carry = 0;
    __syncthreads();
    for (int base = 0; base < N_NODES; base += 4096) {
        int idx = base + tid * 4;
        int v0 = 0, v1 = 0, v2 = 0, v3 = 0;
        if (idx + 3 < N_NODES) {
            int4 t = *reinterpret_cast<const int4*>(g_fill + idx);
            v0 = t.x; v1 = t.y; v2 = t.z; v3 = t.w;
        } else {
            if (idx + 0 < N_NODES) v0 = g_fill[idx + 0];
            if (idx + 1 < N_NODES) v1 = g_fill[idx + 1];
            if (idx + 2 < N_NODES) v2 = g_fill[idx + 2];
            if (idx + 3 < N_NODES) v3 = g_fill[idx + 3];
        }
        int s0 = v0, s1 = s0 + v1, s2 = s1 + v2, s3 = s2 + v3;
        int x = s3;
#pragma unroll
        for (int o = 1; o < 32; o <<= 1) { int t = __shfl_up_sync(~0u, x, o); if (lane >= o) x += t; }
        if (lane == 31) wsum[wid] = x;
        __syncthreads();
        if (wid == 0) {
            int y = wsum[lane];
#pragma unroll
            for (int o = 1; o < 32; o <<= 1) { int t = __shfl_up_sync(~0u, y, o); if (lane >= o) y += t; }
            wsum[lane] = y;
        }
        __syncthreads();
        int excl = carry + (x - s3) + (wid ? wsum[wid - 1] : 0);
        int e0 = excl, e1 = excl + s0, e2 = excl + s1, e3 = excl + s2;
        if (idx + 0 < N_NODES) { g_rowptr[idx + 0] = e0; g_fill[idx + 0] = e0; }
        if (idx + 1 < N_NODES) { g_rowptr[idx + 1] = e1; g_fill[idx + 1] = e1; }
        if (idx + 2 < N_NODES) { g_rowptr[idx + 2] = e2; g_fill[idx + 2] = e2; }
        if (idx + 3 < N_NODES) { g_rowptr[idx + 3] = e3; g_fill[idx + 3] = e3; }
        __syncthreads();
        if (tid == 0) carry += wsum[31];
        __syncthreads();
    }
    if (tid == 0) g_rowptr[N_NODES] = N_EDGES;
}
__global__ void scatter_kernel(const int* __restrict__ src, const int* __restrict__ dst) {
    int e = blockIdx.x * blockDim.x + threadIdx.x;
    if (e < N_EDGES) {
        int d = dst[e];
        int p = atomicAdd(&g_fill[d], 1);
        g_esrc[p] = src[e];
    }
}

// ---------------- fp32 -> bf16 hi/lo conversion ----------------
__global__ void convx_kernel(const float* __restrict__ Xext, int xsel) {
    const float* X = xsel ? g_h0 : Xext;
    int i = blockIdx.x * blockDim.x + threadIdx.x;
    if (i >= (N_NODES * DF) / 4) return;
    float4 v = *reinterpret_cast<const float4*>(X + (size_t)i * 4);
    __nv_bfloat16 h0 = __float2bfloat16(v.x), h1 = __float2bfloat16(v.y);
    __nv_bfloat16 h2 = __float2bfloat16(v.z), h3 = __float2bfloat16(v.w);
    __nv_bfloat16 l0 = __float2bfloat16(v.x - __bfloat162float(h0));
    __nv_bfloat16 l1 = __float2bfloat16(v.y - __bfloat162float(h1));
    __nv_bfloat16 l2 = __float2bfloat16(v.z - __bfloat162float(h2));
    __nv_bfloat16 l3 = __float2bfloat16(v.w - __bfloat162float(h3));
    uint2 ph, pl;
    ph.x = (uint32_t)__bfloat16_as_ushort(h0) | ((uint32_t)__bfloat16_as_ushort(h1) << 16);
    ph.y = (uint32_t)__bfloat16_as_ushort(h2) | ((uint32_t)__bfloat16_as_ushort(h3) << 16);
    pl.x = (uint32_t)__bfloat16_as_ushort(l0) | ((uint32_t)__bfloat16_as_ushort(l1) << 16);
    pl.y = (uint32_t)__bfloat16_as_ushort(l2) | ((uint32_t)__bfloat16_as_ushort(l3) << 16);
    *reinterpret_cast<uint2*>(g_ahi + (size_t)i * 4) = ph;
    *reinterpret_cast<uint2*>(g_alo + (size_t)i * 4) = pl;
}

__global__ void convw_kernel(const float* __restrict__ Wk, const float* __restrict__ Wq,
                             const float* __restrict__ Wv, const float* __restrict__ Ws) {
    int idx = blockIdx.x * blockDim.x + threadIdx.x;
    if (idx >= 4 * 16384) return;
    int m = idx >> 14, rem = idx & 16383, k = rem >> 7, n = rem & 127;
    const float* W = (m == 0) ? Wk : (m == 1) ? Wq : (m == 2) ? Wv : Ws;
    float v = W[k * 128 + n];
    __nv_bfloat16 h = __float2bfloat16(v);
    __nv_bfloat16 l = __float2bfloat16(v - __bfloat162float(h));
    g_bthi[m * 16384 + n * 128 + k] = h;   // transposed [n][k]
    g_btlo[m * 16384 + n * 128 + k] = l;
}

// ---------------- HMMA bf16 hi/lo split GEMM ----------------
// grid = (NTILES, 4): blockIdx.y = which weight matrix (k,q,v,s).
// CTA: 128 rows x 128 cols, K=128 resident. 8 warps, warp tile 64x32.
// D = Ah*Bh + Al*Bh + Ah*Bl (fp32 accum), lo*lo dropped.
#define SM_AH 0
#define SM_AL 32768
#define SM_BH 65536
#define SM_BL 98304
#define SM_TOTAL 131072

__global__ void __launch_bounds__(256, 1) mma_kernel(const float* __restrict__ bias) {
    extern __shared__ char sm[];
    uint32_t sb = smem_u32(sm);
    const int tid = threadIdx.x, wid = tid >> 5, lane = tid & 31;
    const int mat = blockIdx.y;
    const int row0 = blockIdx.x * 128;

    // ---- load tiles: A hi/lo (guarded), B hi/lo ----
    const __nv_bfloat16* Bh_g = g_bthi + (size_t)mat * 16384;
    const __nv_bfloat16* Bl_g = g_btlo + (size_t)mat * 16384;
#pragma unroll
    for (int p = 0; p < 8; p++) {
        int c = tid + p * 256;            // 0..2047
        int r = c >> 4, ch = c & 15;
        uint32_t so = swz(r, ch);
        int gr = row0 + r;
        uint4 vh = make_uint4(0, 0, 0, 0), vl = make_uint4(0, 0, 0, 0);
        if (gr < N_NODES) {
            vh = *reinterpret_cast<const uint4*>(g_ahi + (size_t)gr * DF + ch * 8);
            vl = *reinterpret_cast<const uint4*>(g_alo + (size_t)gr * DF + ch * 8);
        }
        *reinterpret_cast<uint4*>(sm + SM_AH + so) = vh;
        *reinterpret_cast<uint4*>(sm + SM_AL + so) = vl;
        *reinterpret_cast<uint4*>(sm + SM_BH + so) =
            *reinterpret_cast<const uint4*>(Bh_g + (size_t)r * 128 + ch * 8);
        *reinterpret_cast<uint4*>(sm + SM_BL + so) =
            *reinterpret_cast<const uint4*>(Bl_g + (size_t)r * 128 + ch * 8);
    }
    __syncthreads();

    const int wm = (wid & 1) * 64;        // warp row offset in tile
    const int wn = (wid >> 1) * 32;       // warp col offset in tile

    float acc[4][4][4];
#pragma unroll
    for (int i = 0; i < 4; i++)
#pragma unroll
        for (int j = 0; j < 4; j++)
#pragma unroll
            for (int e = 0; e < 4; e++) acc[i][j][e] = 0.f;

    // ldmatrix lane->address components (constant across loop)
    const int a_sel = lane >> 3;              // which 8x8 matrix (0..3)
    const int a_row = (lane & 7) + (a_sel & 1) * 8;
    const int a_chk = a_sel >> 1;             // 0 or 1 (k-halves)
    const int b_l   = lane & 15;              // x2 uses lanes 0..15
    const int b_row = b_l & 7;
    const int b_chk = b_l >> 3;               // 0 or 1

#pragma unroll
    for (int pass = 0; pass < 3; pass++) {
        uint32_t abase = sb + ((pass == 1) ? SM_AL : SM_AH);
        uint32_t bbase = sb + ((pass == 2) ? SM_BL : SM_BH);
#pragma unroll
        for (int k0 = 0; k0 < 128; k0 += 16) {
            int kc = k0 >> 3;
            uint32_t a[4][4], b[4][2];
#pragma unroll
            for (int mt = 0; mt < 4; mt++) {
                int row = wm + mt * 16 + a_row;
                LDSM_X4(a[mt][0], a[mt][1], a[mt][2], a[mt][3], abase + swz(row, kc + a_chk));
            }
#pragma unroll
            for (int nt = 0; nt < 4; nt++) {
                int row = wn + nt * 8 + b_row;
                LDSM_X2(b[nt][0], b[nt][1], bbase + swz(row, kc + b_chk));
            }
#pragma unroll
            for (int mt = 0; mt < 4; mt++)
#pragma unroll
                for (int nt = 0; nt < 4; nt++)
                    MMA16816(acc[mt][nt], a[mt], b[nt]);
        }
    }

    // ---- epilogue ----
    float* Out = (mat == 0) ? g_k : (mat == 1) ? g_q : (mat == 2) ? g_v : g_s;
    const int gq = lane >> 2, tq = lane & 3;
#pragma unroll
    for (int mt = 0; mt < 4; mt++) {
#pragma unroll
        for (int nt = 0; nt < 4; nt++) {
            int col = wn + nt * 8 + tq * 2;
            float bx = 0.f, by = 0.f;
            if (mat == 3) { bx = bias[col]; by = bias[col + 1]; }
            int r0 = row0 + wm + mt * 16 + gq;
            if (r0 < N_NODES) {
                float2 v = make_float2(acc[mt][nt][0] + bx, acc[mt][nt][1] + by);
                *reinterpret_cast<float2*>(Out + (size_t)r0 * DF + col) = v;
            }
            if (r0 + 8 < N_NODES) {
                float2 v = make_float2(acc[mt][nt][2] + bx, acc[mt][nt][3] + by);
                *reinterpret_cast<float2*>(Out + (size_t)(r0 + 8) * DF + col) = v;
            }
        }
    }
}

// ---------------- edge aggregation: one warp per destination node ----------------
__global__ void agg_kernel(int osel, int do_relu) {
    int gw = (blockIdx.x * blockDim.x + threadIdx.x) >> 5;
    if (gw >= N_NODES) return;
    int lane = threadIdx.x & 31;
    float* out = osel ? g_h1 : g_h0;

    size_t fo = (size_t)gw * DF + lane * 4;
    float4 kk = *reinterpret_cast<const float4*>(g_k + fo);
    float4 acc = make_float4(0.f, 0.f, 0.f, 0.f);

    int beg = g_rowptr[gw], end = g_rowptr[gw + 1];
    for (int j = beg; j < end; j++) {
        int s = g_esrc[j];
        size_t so = (size_t)s * DF + lane * 4;
        float4 qq = *reinterpret_cast<const float4*>(g_q + so);
        float4 vv = *reinterpret_cast<const float4*>(g_v + so);
        acc.x += __fdividef(vv.x, 1.f + __expf(-(kk.x + qq.x)));
        acc.y += __fdividef(vv.y, 1.f + __expf(-(kk.y + qq.y)));
        acc.z += __fdividef(vv.z, 1.f + __expf(-(kk.z + qq.z)));
        acc.w += __fdividef(vv.w, 1.f + __expf(-(kk.w + qq.w)));
    }
    float4 ss = *reinterpret_cast<const float4*>(g_s + fo);
    float4 r = make_float4(acc.x + ss.x, acc.y + ss.y, acc.z + ss.z, acc.w + ss.w);
    if (do_relu) {
        r.x = fmaxf(r.x, 0.f); r.y = fmaxf(r.y, 0.f);
        r.z = fmaxf(r.z, 0.f); r.w = fmaxf(r.w, 0.f);
    }
    *reinterpret_cast<float4*>(out + fo) = r;
}

// ---------------- layer 3 (D_OUT = 1) ----------------
__global__ void gemm3_kernel(const float* __restrict__ Wk, const float* __restrict__ Wq,
                             const float* __restrict__ Wv, const float* __restrict__ Ws,
                             const float* __restrict__ bias) {
    int gw = (blockIdx.x * blockDim.x + threadIdx.x) >> 5;
    if (gw >= N_NODES) return;
    int lane = threadIdx.x & 31;
    float4 x4 = *reinterpret_cast<const float4*>(g_h1 + (size_t)gw * DF + lane * 4);
    float4 wk = *reinterpret_cast<const float4*>(Wk + lane * 4);
    float4 wq = *reinterpret_cast<const float4*>(Wq + lane * 4);
    float4 wv = *reinterpret_cast<const float4*>(Wv + lane * 4);
    float4 ws = *reinterpret_cast<const float4*>(Ws + lane * 4);
    float pk = x4.x * wk.x + x4.y * wk.y + x4.z * wk.z + x4.w * wk.w;
    float pq = x4.x * wq.x + x4.y * wq.y + x4.z * wq.z + x4.w * wq.w;
    float pv = x4.x * wv.x + x4.y * wv.y + x4.z * wv.z + x4.w * wv.w;
    float ps = x4.x * ws.x + x4.y * ws.y + x4.z * ws.z + x4.w * ws.w;
#pragma unroll
    for (int o = 16; o; o >>= 1) {
        pk += __shfl_xor_sync(0xffffffffu, pk, o);
        pq += __shfl_xor_sync(0xffffffffu, pq, o);
        pv += __shfl_xor_sync(0xffffffffu, pv, o);
        ps += __shfl_xor_sync(0xffffffffu, ps, o);
    }
    if (lane == 0) {
        g_k[gw] = pk; g_q[gw] = pq; g_v[gw] = pv; g_s[gw] = ps + bias[0];
    }
}

__global__ void agg3_kernel(float* __restrict__ out) {
    int i = blockIdx.x * blockDim.x + threadIdx.x;
    if (i >= N_NODES) return;
    float ki = g_k[i];
    float acc = 0.f;
    int end = g_rowptr[i + 1];
    for (int j = g_rowptr[i]; j < end; j++) {
        int s = g_esrc[j];
        acc += __fdividef(g_v[s], 1.f + __expf(-(ki + g_q[s])));
    }
    out[i] = acc + g_s[i];
}

// ---------------- launch ----------------
extern "C" void kernel_launch(void* const* d_in, const int* in_sizes, int n_in,
                              void* d_out, int out_size) {
    const float* x   = (const float*)d_in[0];
    const int*   ei  = (const int*)d_in[1];
    const int*   src = ei;
    const int*   dst = ei + N_EDGES;
    const float* Wk1 = (const float*)d_in[2];
    const float* Wq1 = (const float*)d_in[3];
    const float* Wv1 = (const float*)d_in[4];
    const float* Ws1 = (const float*)d_in[5];
    const float* b1  = (const float*)d_in[6];
    const float* Wk2 = (const float*)d_in[7];
    const float* Wq2 = (const float*)d_in[8];
    const float* Wv2 = (const float*)d_in[9];
    const float* Ws2 = (const float*)d_in[10];
    const float* b2  = (const float*)d_in[11];
    const float* Wk3 = (const float*)d_in[12];
    const float* Wq3 = (const float*)d_in[13];
    const float* Wv3 = (const float*)d_in[14];
    const float* Ws3 = (const float*)d_in[15];
    const float* b3  = (const float*)d_in[16];
    float* out = (float*)d_out;

    cudaFuncSetAttribute(mma_kernel, cudaFuncAttributeMaxDynamicSharedMemorySize, SM_TOTAL);

    // CSR build (reused by all 3 layers)
    zero_cnt_kernel<<<(N_NODES + 255) / 256, 256>>>();
    hist_kernel<<<(N_EDGES + 255) / 256, 256>>>(dst);
    scan_kernel<<<1, 1024>>>();
    scatter_kernel<<<(N_EDGES + 255) / 256, 256>>>(src, dst);

    dim3 mgrid(NTILES, 4);
    int  conv_blocks = ((N_NODES * DF) / 4 + 255) / 256;
    int  agg_blocks  = (N_NODES * 32 + 255) / 256;

    // layer 1
    convw_kernel<<<256, 256>>>(Wk1, Wq1, Wv1, Ws1);
    convx_kernel<<<conv_blocks, 256>>>(x, 0);
    mma_kernel<<<mgrid, 256, SM_TOTAL>>>(b1);
    agg_kernel<<<agg_blocks, 256>>>(0, 1);
    // layer 2
    convw_kernel<<<256, 256>>>(Wk2, Wq2, Wv2, Ws2);
    convx_kernel<<<conv_blocks, 256>>>(nullptr, 1);
    mma_kernel<<<mgrid, 256, SM_TOTAL>>>(b2);
    agg_kernel<<<agg_blocks, 256>>>(1, 1);
    // layer 3
    gemm3_kernel<<<agg_blocks, 256>>>(Wk3, Wq3, Wv3, Ws3, b3);
    agg3_kernel<<<(N_NODES + 255) / 256, 256>>>(out);
}

// round 7
// speedup vs baseline: 1.8129x; 1.0455x over previous
#include <cuda_runtime.h>
#include <cuda_bf16.h>
#include <cstdint>

#define N_NODES 100000
#define N_EDGES 1600000
#define DF      128
#define NTILES  782          // ceil(100000/128)

// ---------------- scratch (device globals: allocation-free) ----------------
// per-src row: [q(128) | v(128)]; per-dst row: [k(128) | s(128)]
static __device__ float g_qv[(size_t)N_NODES * 256];
static __device__ float g_ks[(size_t)N_NODES * 256];
static __device__ float g_h1[(size_t)N_NODES * DF];
static __device__ int   g_rowptr[N_NODES + 1];
static __device__ int   g_fill[N_NODES];
static __device__ int   g_esrc[N_EDGES];
// bf16 hi/lo split operands
static __device__ __nv_bfloat16 g_ahi[(size_t)N_NODES * DF];
static __device__ __nv_bfloat16 g_alo[(size_t)N_NODES * DF];
static __device__ __nv_bfloat16 g_bthi[4 * 128 * 128];   // transposed [mat][n][k]
static __device__ __nv_bfloat16 g_btlo[4 * 128 * 128];
// layer-3 scalars
static __device__ float g3k[N_NODES], g3q[N_NODES], g3v[N_NODES], g3s[N_NODES];

// ---------------- helpers ----------------
__device__ __forceinline__ uint32_t smem_u32(const void* p) {
    uint32_t a;
    asm("{ .reg .u64 t; cvta.to.shared.u64 t, %1; cvt.u32.u64 %0, t; }" : "=r"(a) : "l"(p));
    return a;
}

// XOR swizzle: tile is [128 rows][128 bf16] = row stride 256B, 16 chunks of 16B.
__device__ __forceinline__ uint32_t swz(int row, int chunk) {
    return (uint32_t)(row * 256 + ((chunk ^ (row & 7)) << 4));
}

#define LDSM_X4(r0, r1, r2, r3, addr) \
    asm volatile("ldmatrix.sync.aligned.m8n8.x4.shared.b16 {%0,%1,%2,%3}, [%4];" \
        : "=r"(r0), "=r"(r1), "=r"(r2), "=r"(r3) : "r"(addr))
#define LDSM_X2(r0, r1, addr) \
    asm volatile("ldmatrix.sync.aligned.m8n8.x2.shared.b16 {%0,%1}, [%2];" \
        : "=r"(r0), "=r"(r1) : "r"(addr))
#define MMA16816(d, a, b) \
    asm volatile("mma.sync.aligned.m16n8k16.row.col.f32.bf16.bf16.f32 " \
        "{%0,%1,%2,%3},{%4,%5,%6,%7},{%8,%9},{%0,%1,%2,%3};" \
        : "+f"((d)[0]), "+f"((d)[1]), "+f"((d)[2]), "+f"((d)[3]) \
        : "r"((a)[0]), "r"((a)[1]), "r"((a)[2]), "r"((a)[3]), "r"((b)[0]), "r"((b)[1]))

__device__ __forceinline__ float fsig(float x) {           // sigmoid
    return __fdividef(1.f, 1.f + __expf(-x));
}

// ---------------- CSR build ----------------
__global__ void zero_cnt_kernel() {
    int i = blockIdx.x * blockDim.x + threadIdx.x;
    if (i < N_NODES) g_fill[i] = 0;
}
__global__ void hist_kernel(const int* __restrict__ dst) {
    int e = blockIdx.x * blockDim.x + threadIdx.x;
    if (e < N_EDGES) atomicAdd(&g_fill[dst[e]], 1);
}
__global__ void scan_kernel() {
    __shared__ int wsum[32];
    __shared__ int carry;
    int tid = threadIdx.x, lane = tid & 31, wid = tid >> 5;
    if (tid == 0) carry = 0;
    __syncthreads();
    for (int base = 0; base < N_NODES; base += 4096) {
        int idx = base + tid * 4;
        int v0 = 0, v1 = 0, v2 = 0, v3 = 0;
        if (idx + 3 < N_NODES) {
            int4 t = *reinterpret_cast<const int4*>(g_fill + idx);
            v0 = t.x; v1 = t.y; v2 = t.z; v3 = t.w;
        } else {
            if (idx + 0 < N_NODES) v0 = g_fill[idx + 0];
            if (idx + 1 < N_NODES) v1 = g_fill[idx + 1];
            if (idx + 2 < N_NODES) v2 = g_fill[idx + 2];
            if (idx + 3 < N_NODES) v3 = g_fill[idx + 3];
        }
        int s0 = v0, s1 = s0 + v1, s2 = s1 + v2, s3 = s2 + v3;
        int x = s3;
#pragma unroll
        for (int o = 1; o < 32; o <<= 1) { int t = __shfl_up_sync(~0u, x, o); if (lane >= o) x += t; }
        if (lane == 31) wsum[wid] = x;
        __syncthreads();
        if (wid == 0) {
            int y = wsum[lane];
#pragma unroll
            for (int o = 1; o < 32; o <<= 1) { int t = __shfl_up_sync(~0u, y, o); if (lane >= o) y += t; }
            wsum[lane] = y;
        }
        __syncthreads();
        int excl = carry + (x - s3) + (wid ? wsum[wid - 1] : 0);
        int e0 = excl, e1 = excl + s0, e2 = excl + s1, e3 = excl + s2;
        if (idx + 0 < N_NODES) { g_rowptr[idx + 0] = e0; g_fill[idx + 0] = e0; }
        if (idx + 1 < N_NODES) { g_rowptr[idx + 1] = e1; g_fill[idx + 1] = e1; }
        if (idx + 2 < N_NODES) { g_rowptr[idx + 2] = e2; g_fill[idx + 2] = e2; }
        if (idx + 3 < N_NODES) { g_rowptr[idx + 3] = e3; g_fill[idx + 3] = e3; }
        __syncthreads();
        if (tid == 0) carry += wsum[31];
        __syncthreads();
    }
    if (tid == 0) g_rowptr[N_NODES] = N_EDGES;
}
__global__ void scatter_kernel(const int* __restrict__ src, const int* __restrict__ dst) {
    int e = blockIdx.x * blockDim.x + threadIdx.x;
    if (e < N_EDGES) {
        int d = dst[e];
        int p = atomicAdd(&g_fill[d], 1);
        g_esrc[p] = src[e];
    }
}

// ---------------- fp32 -> bf16 hi/lo conversion (layer-1 input only) ----------
__global__ void convx_kernel(const float* __restrict__ X) {
    int i = blockIdx.x * blockDim.x + threadIdx.x;
    if (i >= (N_NODES * DF) / 4) return;
    float4 v = *reinterpret_cast<const float4*>(X + (size_t)i * 4);
    __nv_bfloat16 h0 = __float2bfloat16(v.x), h1 = __float2bfloat16(v.y);
    __nv_bfloat16 h2 = __float2bfloat16(v.z), h3 = __float2bfloat16(v.w);
    __nv_bfloat16 l0 = __float2bfloat16(v.x - __bfloat162float(h0));
    __nv_bfloat16 l1 = __float2bfloat16(v.y - __bfloat162float(h1));
    __nv_bfloat16 l2 = __float2bfloat16(v.z - __bfloat162float(h2));
    __nv_bfloat16 l3 = __float2bfloat16(v.w - __bfloat162float(h3));
    uint2 ph, pl;
    ph.x = (uint32_t)__bfloat16_as_ushort(h0) | ((uint32_t)__bfloat16_as_ushort(h1) << 16);
    ph.y = (uint32_t)__bfloat16_as_ushort(h2) | ((uint32_t)__bfloat16_as_ushort(h3) << 16);
    pl.x = (uint32_t)__bfloat16_as_ushort(l0) | ((uint32_t)__bfloat16_as_ushort(l1) << 16);
    pl.y = (uint32_t)__bfloat16_as_ushort(l2) | ((uint32_t)__bfloat16_as_ushort(l3) << 16);
    *reinterpret_cast<uint2*>(g_ahi + (size_t)i * 4) = ph;
    *reinterpret_cast<uint2*>(g_alo + (size_t)i * 4) = pl;
}

__global__ void convw_kernel(const float* __restrict__ Wk, const float* __restrict__ Wq,
                             const float* __restrict__ Wv, const float* __restrict__ Ws) {
    int idx = blockIdx.x * blockDim.x + threadIdx.x;
    if (idx >= 4 * 16384) return;
    int m = idx >> 14, rem = idx & 16383, k = rem >> 7, n = rem & 127;
    const float* W = (m == 0) ? Wk : (m == 1) ? Wq : (m == 2) ? Wv : Ws;
    float v = W[k * 128 + n];
    __nv_bfloat16 h = __float2bfloat16(v);
    __nv_bfloat16 l = __float2bfloat16(v - __bfloat162float(h));
    g_bthi[m * 16384 + n * 128 + k] = h;   // transposed [n][k]
    g_btlo[m * 16384 + n * 128 + k] = l;
}

// ---------------- HMMA bf16 hi/lo split GEMM ----------------
// grid = (NTILES, 4): blockIdx.y = which weight matrix (k,q,v,s).
// Outputs interleaved: k -> g_ks[:,0:128], s -> g_ks[:,128:256],
//                      q -> g_qv[:,0:128], v -> g_qv[:,128:256].
#define SM_AH 0
#define SM_AL 32768
#define SM_BH 65536
#define SM_BL 98304
#define SM_TOTAL 131072

__global__ void __launch_bounds__(256, 1) mma_kernel(const float* __restrict__ bias) {
    extern __shared__ char sm[];
    uint32_t sb = smem_u32(sm);
    const int tid = threadIdx.x, wid = tid >> 5, lane = tid & 31;
    const int mat = blockIdx.y;
    const int row0 = blockIdx.x * 128;

    const __nv_bfloat16* Bh_g = g_bthi + (size_t)mat * 16384;
    const __nv_bfloat16* Bl_g = g_btlo + (size_t)mat * 16384;
#pragma unroll
    for (int p = 0; p < 8; p++) {
        int c = tid + p * 256;            // 0..2047
        int r = c >> 4, ch = c & 15;
        uint32_t so = swz(r, ch);
        int gr = row0 + r;
        uint4 vh = make_uint4(0, 0, 0, 0), vl = make_uint4(0, 0, 0, 0);
        if (gr < N_NODES) {
            vh = *reinterpret_cast<const uint4*>(g_ahi + (size_t)gr * DF + ch * 8);
            vl = *reinterpret_cast<const uint4*>(g_alo + (size_t)gr * DF + ch * 8);
        }
        *reinterpret_cast<uint4*>(sm + SM_AH + so) = vh;
        *reinterpret_cast<uint4*>(sm + SM_AL + so) = vl;
        *reinterpret_cast<uint4*>(sm + SM_BH + so) =
            *reinterpret_cast<const uint4*>(Bh_g + (size_t)r * 128 + ch * 8);
        *reinterpret_cast<uint4*>(sm + SM_BL + so) =
            *reinterpret_cast<const uint4*>(Bl_g + (size_t)r * 128 + ch * 8);
    }
    __syncthreads();

    const int wm = (wid & 1) * 64;
    const int wn = (wid >> 1) * 32;

    float acc[4][4][4];
#pragma unroll
    for (int i = 0; i < 4; i++)
#pragma unroll
        for (int j = 0; j < 4; j++)
#pragma unroll
            for (int e = 0; e < 4; e++) acc[i][j][e] = 0.f;

    const int a_sel = lane >> 3;
    const int a_row = (lane & 7) + (a_sel & 1) * 8;
    const int a_chk = a_sel >> 1;
    const int b_l   = lane & 15;
    const int b_row = b_l & 7;
    const int b_chk = b_l >> 3;

#pragma unroll
    for (int pass = 0; pass < 3; pass++) {
        uint32_t abase = sb + ((pass == 1) ? SM_AL : SM_AH);
        uint32_t bbase = sb + ((pass == 2) ? SM_BL : SM_BH);
#pragma unroll
        for (int k0 = 0; k0 < 128; k0 += 16) {
            int kc = k0 >> 3;
            uint32_t a[4][4], b[4][2];
#pragma unroll
            for (int mt = 0; mt < 4; mt++) {
                int row = wm + mt * 16 + a_row;
                LDSM_X4(a[mt][0], a[mt][1], a[mt][2], a[mt][3], abase + swz(row, kc + a_chk));
            }
#pragma unroll
            for (int nt = 0; nt < 4; nt++) {
                int row = wn + nt * 8 + b_row;
                LDSM_X2(b[nt][0], b[nt][1], bbase + swz(row, kc + b_chk));
            }
#pragma unroll
            for (int mt = 0; mt < 4; mt++)
#pragma unroll
                for (int nt = 0; nt < 4; nt++)
                    MMA16816(acc[mt][nt], a[mt], b[nt]);
        }
    }

    // epilogue: interleaved outputs (row stride 256 floats)
    float* Out = (mat == 0) ? g_ks : (mat == 1) ? g_qv : (mat == 2) ? (g_qv + 128) : (g_ks + 128);
    const int gq = lane >> 2, tq = lane & 3;
#pragma unroll
    for (int mt = 0; mt < 4; mt++) {
#pragma unroll
        for (int nt = 0; nt < 4; nt++) {
            int col = wn + nt * 8 + tq * 2;
            float bx = 0.f, by = 0.f;
            if (mat == 3) { bx = bias[col]; by = bias[col + 1]; }
            int r0 = row0 + wm + mt * 16 + gq;
            if (r0 < N_NODES) {
                float2 v = make_float2(acc[mt][nt][0] + bx, acc[mt][nt][1] + by);
                *reinterpret_cast<float2*>(Out + (size_t)r0 * 256 + col) = v;
            }
            if (r0 + 8 < N_NODES) {
                float2 v = make_float2(acc[mt][nt][2] + bx, acc[mt][nt][3] + by);
                *reinterpret_cast<float2*>(Out + (size_t)(r0 + 8) * 256 + col) = v;
            }
        }
    }
}

// ---------------- edge aggregation: one warp per destination node ----------------
// Unroll-4 software pipeline for MLP. split_out=1 -> write bf16 hi/lo (next
// layer's MMA A operand); split_out=0 -> write fp32 g_h1. ReLU always applied.
__device__ __forceinline__ void gate_acc(float4& acc, const float4 kk,
                                         const float* __restrict__ qv, int lane4) {
    float4 qq = *reinterpret_cast<const float4*>(qv + lane4);
    float4 vv = *reinterpret_cast<const float4*>(qv + 128 + lane4);
    acc.x += fsig(kk.x + qq.x) * vv.x;
    acc.y += fsig(kk.y + qq.y) * vv.y;
    acc.z += fsig(kk.z + qq.z) * vv.z;
    acc.w += fsig(kk.w + qq.w) * vv.w;
}

__global__ void __launch_bounds__(256) agg_kernel(int split_out) {
    int gw = (blockIdx.x * blockDim.x + threadIdx.x) >> 5;
    if (gw >= N_NODES) return;
    int lane = threadIdx.x & 31;
    int lane4 = lane * 4;

    const float* ks_row = g_ks + (size_t)gw * 256;
    float4 kk = *reinterpret_cast<const float4*>(ks_row + lane4);
    float4 a0 = make_float4(0.f, 0.f, 0.f, 0.f);
    float4 a1 = make_float4(0.f, 0.f, 0.f, 0.f);

    int j = g_rowptr[gw], end = g_rowptr[gw + 1];
    for (; j + 4 <= end; j += 4) {
        int s0 = g_esrc[j], s1 = g_esrc[j + 1], s2 = g_esrc[j + 2], s3 = g_esrc[j + 3];
        const float* r0 = g_qv + (size_t)s0 * 256;
        const float* r1 = g_qv + (size_t)s1 * 256;
        const float* r2 = g_qv + (size_t)s2 * 256;
        const float* r3 = g_qv + (size_t)s3 * 256;
        // touch all 8 rows (loads issue back-to-back; compute follows)
        float4 q0 = *reinterpret_cast<const float4*>(r0 + lane4);
        float4 v0 = *reinterpret_cast<const float4*>(r0 + 128 + lane4);
        float4 q1 = *reinterpret_cast<const float4*>(r1 + lane4);
        float4 v1 = *reinterpret_cast<const float4*>(r1 + 128 + lane4);
        float4 q2 = *reinterpret_cast<const float4*>(r2 + lane4);
        float4 v2 = *reinterpret_cast<const float4*>(r2 + 128 + lane4);
        float4 q3 = *reinterpret_cast<const float4*>(r3 + lane4);
        float4 v3 = *reinterpret_cast<const float4*>(r3 + 128 + lane4);
        a0.x += fsig(kk.x + q0.x) * v0.x; a0.y += fsig(kk.y + q0.y) * v0.y;
        a0.z += fsig(kk.z + q0.z) * v0.z; a0.w += fsig(kk.w + q0.w) * v0.w;
        a1.x += fsig(kk.x + q1.x) * v1.x; a1.y += fsig(kk.y + q1.y) * v1.y;
        a1.z += fsig(kk.z + q1.z) * v1.z; a1.w += fsig(kk.w + q1.w) * v1.w;
        a0.x += fsig(kk.x + q2.x) * v2.x; a0.y += fsig(kk.y + q2.y) * v2.y;
        a0.z += fsig(kk.z + q2.z) * v2.z; a0.w += fsig(kk.w + q2.w) * v2.w;
        a1.x += fsig(kk.x + q3.x) * v3.x; a1.y += fsig(kk.y + q3.y) * v3.y;
        a1.z += fsig(kk.z + q3.z) * v3.z; a1.w += fsig(kk.w + q3.w) * v3.w;
    }
    for (; j < end; j++) {
        int s = g_esrc[j];
        gate_acc(a0, kk, g_qv + (size_t)s * 256, lane4);
    }

    float4 ss = *reinterpret_cast<const float4*>(ks_row + 128 + lane4);
    float4 r = make_float4(fmaxf(a0.x + a1.x + ss.x, 0.f),
                           fmaxf(a0.y + a1.y + ss.y, 0.f),
                           fmaxf(a0.z + a1.z + ss.z, 0.f),
                           fmaxf(a0.w + a1.w + ss.w, 0.f));
    size_t fo = (size_t)gw * DF + lane4;
    if (split_out) {
        __nv_bfloat16 h0 = __float2bfloat16(r.x), h1 = __float2bfloat16(r.y);
        __nv_bfloat16 h2 = __float2bfloat16(r.z), h3 = __float2bfloat16(r.w);
        __nv_bfloat16 l0 = __float2bfloat16(r.x - __bfloat162float(h0));
        __nv_bfloat16 l1 = __float2bfloat16(r.y - __bfloat162float(h1));
        __nv_bfloat16 l2 = __float2bfloat16(r.z - __bfloat162float(h2));
        __nv_bfloat16 l3 = __float2bfloat16(r.w - __bfloat162float(h3));
        uint2 ph, pl;
        ph.x = (uint32_t)__bfloat16_as_ushort(h0) | ((uint32_t)__bfloat16_as_ushort(h1) << 16);
        ph.y = (uint32_t)__bfloat16_as_ushort(h2) | ((uint32_t)__bfloat16_as_ushort(h3) << 16);
        pl.x = (uint32_t)__bfloat16_as_ushort(l0) | ((uint32_t)__bfloat16_as_ushort(l1) << 16);
        pl.y = (uint32_t)__bfloat16_as_ushort(l2) | ((uint32_t)__bfloat16_as_ushort(l3) << 16);
        *reinterpret_cast<uint2*>(g_ahi + fo) = ph;
        *reinterpret_cast<uint2*>(g_alo + fo) = pl;
    } else {
        *reinterpret_cast<float4*>(g_h1 + fo) = r;
    }
}

// ---------------- layer 3 (D_OUT = 1) ----------------
__global__ void gemm3_kernel(const float* __restrict__ Wk, const float* __restrict__ Wq,
                             const float* __restrict__ Wv, const float* __restrict__ Ws,
                             const float* __restrict__ bias) {
    int gw = (blockIdx.x * blockDim.x + threadIdx.x) >> 5;
    if (gw >= N_NODES) return;
    int lane = threadIdx.x & 31;
    float4 x4 = *reinterpret_cast<const float4*>(g_h1 + (size_t)gw * DF + lane * 4);
    float4 wk = *reinterpret_cast<const float4*>(Wk + lane * 4);
    float4 wq = *reinterpret_cast<const float4*>(Wq + lane * 4);
    float4 wv = *reinterpret_cast<const float4*>(Wv + lane * 4);
    float4 ws = *reinterpret_cast<const float4*>(Ws + lane * 4);
    float pk = x4.x * wk.x + x4.y * wk.y + x4.z * wk.z + x4.w * wk.w;
    float pq = x4.x * wq.x + x4.y * wq.y + x4.z * wq.z + x4.w * wq.w;
    float pv = x4.x * wv.x + x4.y * wv.y + x4.z * wv.z + x4.w * wv.w;
    float ps = x4.x * ws.x + x4.y * ws.y + x4.z * ws.z + x4.w * ws.w;
#pragma unroll
    for (int o = 16; o; o >>= 1) {
        pk += __shfl_xor_sync(0xffffffffu, pk, o);
        pq += __shfl_xor_sync(0xffffffffu, pq, o);
        pv += __shfl_xor_sync(0xffffffffu, pv, o);
        ps += __shfl_xor_sync(0xffffffffu, ps, o);
    }
    if (lane == 0) {
        g3k[gw] = pk; g3q[gw] = pq; g3v[gw] = pv; g3s[gw] = ps + bias[0];
    }
}

__global__ void agg3_kernel(float* __restrict__ out) {
    int i = blockIdx.x * blockDim.x + threadIdx.x;
    if (i >= N_NODES) return;
    float ki = g3k[i];
    float acc = 0.f;
    int end = g_rowptr[i + 1];
    for (int j = g_rowptr[i]; j < end; j++) {
        int s = g_esrc[j];
        acc += fsig(ki + g3q[s]) * g3v[s];
    }
    out[i] = acc + g3s[i];
}

// ---------------- launch ----------------
extern "C" void kernel_launch(void* const* d_in, const int* in_sizes, int n_in,
                              void* d_out, int out_size) {
    const float* x   = (const float*)d_in[0];
    const int*   ei  = (const int*)d_in[1];
    const int*   src = ei;
    const int*   dst = ei + N_EDGES;
    const float* Wk1 = (const float*)d_in[2];
    const float* Wq1 = (const float*)d_in[3];
    const float* Wv1 = (const float*)d_in[4];
    const float* Ws1 = (const float*)d_in[5];
    const float* b1  = (const float*)d_in[6];
    const float* Wk2 = (const float*)d_in[7];
    const float* Wq2 = (const float*)d_in[8];
    const float* Wv2 = (const float*)d_in[9];
    const float* Ws2 = (const float*)d_in[10];
    const float* b2  = (const float*)d_in[11];
    const float* Wk3 = (const float*)d_in[12];
    const float* Wq3 = (const float*)d_in[13];
    const float* Wv3 = (const float*)d_in[14];
    const float* Ws3 = (const float*)d_in[15];
    const float* b3  = (const float*)d_in[16];
    float* out = (float*)d_out;

    cudaFuncSetAttribute(mma_kernel, cudaFuncAttributeMaxDynamicSharedMemorySize, SM_TOTAL);

    // CSR build (reused by all 3 layers)
    zero_cnt_kernel<<<(N_NODES + 255) / 256, 256>>>();
    hist_kernel<<<(N_EDGES + 255) / 256, 256>>>(dst);
    scan_kernel<<<1, 1024>>>();
    scatter_kernel<<<(N_EDGES + 255) / 256, 256>>>(src, dst);

    dim3 mgrid(NTILES, 4);
    int  conv_blocks = ((N_NODES * DF) / 4 + 255) / 256;
    int  agg_blocks  = (N_NODES * 32 + 255) / 256;

    // layer 1
    convw_kernel<<<256, 256>>>(Wk1, Wq1, Wv1, Ws1);
    convx_kernel<<<conv_blocks, 256>>>(x);
    mma_kernel<<<mgrid, 256, SM_TOTAL>>>(b1);
    agg_kernel<<<agg_blocks, 256>>>(1);       // writes bf16 hi/lo for layer 2
    // layer 2
    convw_kernel<<<256, 256>>>(Wk2, Wq2, Wv2, Ws2);
    mma_kernel<<<mgrid, 256, SM_TOTAL>>>(b2);
    agg_kernel<<<agg_blocks, 256>>>(0);       // writes fp32 h1 for layer 3
    // layer 3
    gemm3_kernel<<<agg_blocks, 256>>>(Wk3, Wq3, Wv3, Ws3, b3);
    agg3_kernel<<<(N_NODES + 255) / 256, 256>>>(out);
}

// round 9
// speedup vs baseline: 2.0520x; 1.1319x over previous
#include <cuda_runtime.h>
#include <cuda_bf16.h>
#include <cuda_fp16.h>
#include <cstdint>

#define N_NODES 100000
#define N_EDGES 1600000
#define DF      128
#define NTILES  782          // ceil(100000/128)

// ---------------- scratch (device globals: allocation-free) ----------------
// per-src row (fp16): [q(128) | v(128)]  -> 512B/node, 51MB total (L2-resident)
static __device__ __half g_qvh[(size_t)N_NODES * 256];
// per-dst row (fp32): [k(128) | s(128)]
static __device__ float g_ks[(size_t)N_NODES * 256];
static __device__ float g_h1[(size_t)N_NODES * DF];
static __device__ int   g_rowptr[N_NODES + 1];
static __device__ int   g_fill[N_NODES];
static __device__ int   g_esrc[N_EDGES];
// bf16 hi/lo split operands
static __device__ __nv_bfloat16 g_ahi[(size_t)N_NODES * DF];
static __device__ __nv_bfloat16 g_alo[(size_t)N_NODES * DF];
static __device__ __nv_bfloat16 g_bthi[4 * 128 * 128];   // transposed [mat][n][k]
static __device__ __nv_bfloat16 g_btlo[4 * 128 * 128];
// layer-3 scalars
static __device__ float g3k[N_NODES], g3q[N_NODES], g3v[N_NODES], g3s[N_NODES];

// ---------------- helpers ----------------
__device__ __forceinline__ uint32_t smem_u32(const void* p) {
    uint32_t a;
    asm("{ .reg .u64 t; cvta.to.shared.u64 t, %1; cvt.u32.u64 %0, t; }" : "=r"(a) : "l"(p));
    return a;
}

// XOR swizzle: tile is [128 rows][128 bf16] = row stride 256B, 16 chunks of 16B.
__device__ __forceinline__ uint32_t swz(int row, int chunk) {
    return (uint32_t)(row * 256 + ((chunk ^ (row & 7)) << 4));
}

#define LDSM_X4(r0, r1, r2, r3, addr) \
    asm volatile("ldmatrix.sync.aligned.m8n8.x4.shared.b16 {%0,%1,%2,%3}, [%4];" \
        : "=r"(r0), "=r"(r1), "=r"(r2), "=r"(r3) : "r"(addr))
#define LDSM_X2(r0, r1, addr) \
    asm volatile("ldmatrix.sync.aligned.m8n8.x2.shared.b16 {%0,%1}, [%2];" \
        : "=r"(r0), "=r"(r1) : "r"(addr))
#define MMA16816(d, a, b) \
    asm volatile("mma.sync.aligned.m16n8k16.row.col.f32.bf16.bf16.f32 " \
        "{%0,%1,%2,%3},{%4,%5,%6,%7},{%8,%9},{%0,%1,%2,%3};" \
        : "+f"((d)[0]), "+f"((d)[1]), "+f"((d)[2]), "+f"((d)[3]) \
        : "r"((a)[0]), "r"((a)[1]), "r"((a)[2]), "r"((a)[3]), "r"((b)[0]), "r"((b)[1]))

// exact sigmoid (2 MUFU: EX2 + RCP)
__device__ __forceinline__ float fsig(float x) {
    return __fdividef(1.f, 1.f + __expf(-x));
}

// ---------------- CSR build ----------------
__global__ void zero_cnt_kernel() {
    int i = blockIdx.x * blockDim.x + threadIdx.x;
    if (i < N_NODES) g_fill[i] = 0;
}
__global__ void hist_kernel(const int* __restrict__ dst) {
    int e = blockIdx.x * blockDim.x + threadIdx.x;
    if (e < N_EDGES) atomicAdd(&g_fill[dst[e]], 1);
}
__global__ void scan_kernel() {
    __shared__ int wsum[32];
    __shared__ int carry;
    int tid = threadIdx.x, lane = tid & 31, wid = tid >> 5;
    if (tid == 0) carry = 0;
    __syncthreads();
    for (int base = 0; base < N_NODES; base += 4096) {
        int idx = base + tid * 4;
        int v0 = 0, v1 = 0, v2 = 0, v3 = 0;
        if (idx + 3 < N_NODES) {
            int4 t = *reinterpret_cast<const int4*>(g_fill + idx);
            v0 = t.x; v1 = t.y; v2 = t.z; v3 = t.w;
        } else {
            if (idx + 0 < N_NODES) v0 = g_fill[idx + 0];
            if (idx + 1 < N_NODES) v1 = g_fill[idx + 1];
            if (idx + 2 < N_NODES) v2 = g_fill[idx + 2];
            if (idx + 3 < N_NODES) v3 = g_fill[idx + 3];
        }
        int s0 = v0, s1 = s0 + v1, s2 = s1 + v2, s3 = s2 + v3;
        int x = s3;
#pragma unroll
        for (int o = 1; o < 32; o <<= 1) { int t = __shfl_up_sync(~0u, x, o); if (lane >= o) x += t; }
        if (lane == 31) wsum[wid] = x;
        __syncthreads();
        if (wid == 0) {
            int y = wsum[lane];
#pragma unroll
            for (int o = 1; o < 32; o <<= 1) { int t = __shfl_up_sync(~0u, y, o); if (lane >= o) y += t; }
            wsum[lane] = y;
        }
        __syncthreads();
        int excl = carry + (x - s3) + (wid ? wsum[wid - 1] : 0);
        int e0 = excl, e1 = excl + s0, e2 = excl + s1, e3 = excl + s2;
        if (idx + 0 < N_NODES) { g_rowptr[idx + 0] = e0; g_fill[idx + 0] = e0; }
        if (idx + 1 < N_NODES) { g_rowptr[idx + 1] = e1; g_fill[idx + 1] = e1; }
        if (idx + 2 < N_NODES) { g_rowptr[idx + 2] = e2; g_fill[idx + 2] = e2; }
        if (idx + 3 < N_NODES) { g_rowptr[idx + 3] = e3; g_fill[idx + 3] = e3; }
        __syncthreads();
        if (tid == 0) carry += wsum[31];
        __syncthreads();
    }
    if (tid == 0) g_rowptr[N_NODES] = N_EDGES;
}
__global__ void scatter_kernel(const int* __restrict__ src, const int* __restrict__ dst) {
    int e = blockIdx.x * blockDim.x + threadIdx.x;
    if (e < N_EDGES) {
        int d = dst[e];
        int p = atomicAdd(&g_fill[d], 1);
        g_esrc[p] = src[e];
    }
}

// ---------------- fp32 -> bf16 hi/lo conversion (layer-1 input only) ----------
__global__ void convx_kernel(const float* __restrict__ X) {
    int i = blockIdx.x * blockDim.x + threadIdx.x;
    if (i >= (N_NODES * DF) / 4) return;
    float4 v = *reinterpret_cast<const float4*>(X + (size_t)i * 4);
    __nv_bfloat16 h0 = __float2bfloat16(v.x), h1 = __float2bfloat16(v.y);
    __nv_bfloat16 h2 = __float2bfloat16(v.z), h3 = __float2bfloat16(v.w);
    __nv_bfloat16 l0 = __float2bfloat16(v.x - __bfloat162float(h0));
    __nv_bfloat16 l1 = __float2bfloat16(v.y - __bfloat162float(h1));
    __nv_bfloat16 l2 = __float2bfloat16(v.z - __bfloat162float(h2));
    __nv_bfloat16 l3 = __float2bfloat16(v.w - __bfloat162float(h3));
    uint2 ph, pl;
    ph.x = (uint32_t)__bfloat16_as_ushort(h0) | ((uint32_t)__bfloat16_as_ushort(h1) << 16);
    ph.y = (uint32_t)__bfloat16_as_ushort(h2) | ((uint32_t)__bfloat16_as_ushort(h3) << 16);
    pl.x = (uint32_t)__bfloat16_as_ushort(l0) | ((uint32_t)__bfloat16_as_ushort(l1) << 16);
    pl.y = (uint32_t)__bfloat16_as_ushort(l2) | ((uint32_t)__bfloat16_as_ushort(l3) << 16);
    *reinterpret_cast<uint2*>(g_ahi + (size_t)i * 4) = ph;
    *reinterpret_cast<uint2*>(g_alo + (size_t)i * 4) = pl;
}

__global__ void convw_kernel(const float* __restrict__ Wk, const float* __restrict__ Wq,
                             const float* __restrict__ Wv, const float* __restrict__ Ws) {
    int idx = blockIdx.x * blockDim.x + threadIdx.x;
    if (idx >= 4 * 16384) return;
    int m = idx >> 14, rem = idx & 16383, k = rem >> 7, n = rem & 127;
    const float* W = (m == 0) ? Wk : (m == 1) ? Wq : (m == 2) ? Wv : Ws;
    float v = W[k * 128 + n];
    __nv_bfloat16 h = __float2bfloat16(v);
    __nv_bfloat16 l = __float2bfloat16(v - __bfloat162float(h));
    g_bthi[m * 16384 + n * 128 + k] = h;   // transposed [n][k]
    g_btlo[m * 16384 + n * 128 + k] = l;
}

// ---------------- HMMA bf16 hi/lo split GEMM ----------------
// grid = (NTILES, 4): blockIdx.y = which weight matrix (k,q,v,s).
// Outputs: k -> g_ks[:,0:128] fp32, s -> g_ks[:,128:256] fp32,
//          q -> g_qvh[:,0:128] fp16, v -> g_qvh[:,128:256] fp16.
#define SM_AH 0
#define SM_AL 32768
#define SM_BH 65536
#define SM_BL 98304
#define SM_TOTAL 131072

__global__ void __launch_bounds__(256, 1) mma_kernel(const float* __restrict__ bias) {
    extern __shared__ char sm[];
    uint32_t sb = smem_u32(sm);
    const int tid = threadIdx.x, wid = tid >> 5, lane = tid & 31;
    const int mat = blockIdx.y;
    const int row0 = blockIdx.x * 128;

    const __nv_bfloat16* Bh_g = g_bthi + (size_t)mat * 16384;
    const __nv_bfloat16* Bl_g = g_btlo + (size_t)mat * 16384;
#pragma unroll
    for (int p = 0; p < 8; p++) {
        int c = tid + p * 256;            // 0..2047
        int r = c >> 4, ch = c & 15;
        uint32_t so = swz(r, ch);
        int gr = row0 + r;
        uint4 vh = make_uint4(0, 0, 0, 0), vl = make_uint4(0, 0, 0, 0);
        if (gr < N_NODES) {
            vh = *reinterpret_cast<const uint4*>(g_ahi + (size_t)gr * DF + ch * 8);
            vl = *reinterpret_cast<const uint4*>(g_alo + (size_t)gr * DF + ch * 8);
        }
        *reinterpret_cast<uint4*>(sm + SM_AH + so) = vh;
        *reinterpret_cast<uint4*>(sm + SM_AL + so) = vl;
        *reinterpret_cast<uint4*>(sm + SM_BH + so) =
            *reinterpret_cast<const uint4*>(Bh_g + (size_t)r * 128 + ch * 8);
        *reinterpret_cast<uint4*>(sm + SM_BL + so) =
            *reinterpret_cast<const uint4*>(Bl_g + (size_t)r * 128 + ch * 8);
    }
    __syncthreads();

    const int wm = (wid & 1) * 64;
    const int wn = (wid >> 1) * 32;

    float acc[4][4][4];
#pragma unroll
    for (int i = 0; i < 4; i++)
#pragma unroll
        for (int j = 0; j < 4; j++)
#pragma unroll
            for (int e = 0; e < 4; e++) acc[i][j][e] = 0.f;

    const int a_sel = lane >> 3;
    const int a_row = (lane & 7) + (a_sel & 1) * 8;
    const int a_chk = a_sel >> 1;
    const int b_l   = lane & 15;
    const int b_row = b_l & 7;
    const int b_chk = b_l >> 3;

#pragma unroll
    for (int pass = 0; pass < 3; pass++) {
        uint32_t abase = sb + ((pass == 1) ? SM_AL : SM_AH);
        uint32_t bbase = sb + ((pass == 2) ? SM_BL : SM_BH);
#pragma unroll
        for (int k0 = 0; k0 < 128; k0 += 16) {
            int kc = k0 >> 3;
            uint32_t a[4][4], b[4][2];
#pragma unroll
            for (int mt = 0; mt < 4; mt++) {
                int row = wm + mt * 16 + a_row;
                LDSM_X4(a[mt][0], a[mt][1], a[mt][2], a[mt][3], abase + swz(row, kc + a_chk));
            }
#pragma unroll
            for (int nt = 0; nt < 4; nt++) {
                int row = wn + nt * 8 + b_row;
                LDSM_X2(b[nt][0], b[nt][1], bbase + swz(row, kc + b_chk));
            }
#pragma unroll
            for (int mt = 0; mt < 4; mt++)
#pragma unroll
                for (int nt = 0; nt < 4; nt++)
                    MMA16816(acc[mt][nt], a[mt], b[nt]);
        }
    }

    // epilogue
    const int gq = lane >> 2, tq = lane & 3;
    const bool is_qv = (mat == 1) || (mat == 2);
    float* OutF = (mat == 0) ? g_ks : (g_ks + 128);             // k or s
    __half* OutH = (mat == 1) ? g_qvh : (g_qvh + 128);          // q or v
#pragma unroll
    for (int mt = 0; mt < 4; mt++) {
#pragma unroll
        for (int nt = 0; nt < 4; nt++) {
            int col = wn + nt * 8 + tq * 2;
            float bx = 0.f, by = 0.f;
            if (mat == 3) { bx = bias[col]; by = bias[col + 1]; }
            int r0 = row0 + wm + mt * 16 + gq;
            if (is_qv) {
                if (r0 < N_NODES) {
                    __half2 h = __floats2half2_rn(acc[mt][nt][0], acc[mt][nt][1]);
                    *reinterpret_cast<__half2*>(OutH + (size_t)r0 * 256 + col) = h;
                }
                if (r0 + 8 < N_NODES) {
                    __half2 h = __floats2half2_rn(acc[mt][nt][2], acc[mt][nt][3]);
                    *reinterpret_cast<__half2*>(OutH + (size_t)(r0 + 8) * 256 + col) = h;
                }
            } else {
                if (r0 < N_NODES) {
                    float2 v = make_float2(acc[mt][nt][0] + bx, acc[mt][nt][1] + by);
                    *reinterpret_cast<float2*>(OutF + (size_t)r0 * 256 + col) = v;
                }
                if (r0 + 8 < N_NODES) {
                    float2 v = make_float2(acc[mt][nt][2] + bx, acc[mt][nt][3] + by);
                    *reinterpret_cast<float2*>(OutF + (size_t)(r0 + 8) * 256 + col) = v;
                }
            }
        }
    }
}

// ---------------- edge aggregation: one warp per destination node ----------------
// fp16 q|v rows (L2-resident), exact sigmoid, unroll-4 for MLP.
__device__ __forceinline__ void gate4(float4& acc, const float4 kk, uint2 qraw, uint2 vraw) {
    float2 q01 = __half22float2(*reinterpret_cast<__half2*>(&qraw.x));
    float2 q23 = __half22float2(*reinterpret_cast<__half2*>(&qraw.y));
    float2 v01 = __half22float2(*reinterpret_cast<__half2*>(&vraw.x));
    float2 v23 = __half22float2(*reinterpret_cast<__half2*>(&vraw.y));
    acc.x = fmaf(fsig(kk.x + q01.x), v01.x, acc.x);
    acc.y = fmaf(fsig(kk.y + q01.y), v01.y, acc.y);
    acc.z = fmaf(fsig(kk.z + q23.x), v23.x, acc.z);
    acc.w = fmaf(fsig(kk.w + q23.y), v23.y, acc.w);
}

__global__ void __launch_bounds__(256) agg_kernel(int split_out) {
    int gw = (blockIdx.x * blockDim.x + threadIdx.x) >> 5;
    if (gw >= N_NODES) return;
    int lane = threadIdx.x & 31;
    int lane4 = lane * 4;

    const float* ks_row = g_ks + (size_t)gw * 256;
    float4 kk = *reinterpret_cast<const float4*>(ks_row + lane4);
    float4 a0 = make_float4(0.f, 0.f, 0.f, 0.f);
    float4 a1 = make_float4(0.f, 0.f, 0.f, 0.f);

    int j = g_rowptr[gw], end = g_rowptr[gw + 1];
    for (; j + 4 <= end; j += 4) {
        int s0 = g_esrc[j], s1 = g_esrc[j + 1], s2 = g_esrc[j + 2], s3 = g_esrc[j + 3];
        const __half* r0 = g_qvh + (size_t)s0 * 256;
        const __half* r1 = g_qvh + (size_t)s1 * 256;
        const __half* r2 = g_qvh + (size_t)s2 * 256;
        const __half* r3 = g_qvh + (size_t)s3 * 256;
        uint2 q0 = *reinterpret_cast<const uint2*>(r0 + lane4);
        uint2 v0 = *reinterpret_cast<const uint2*>(r0 + 128 + lane4);
        uint2 q1 = *reinterpret_cast<const uint2*>(r1 + lane4);
        uint2 v1 = *reinterpret_cast<const uint2*>(r1 + 128 + lane4);
        uint2 q2 = *reinterpret_cast<const uint2*>(r2 + lane4);
        uint2 v2 = *reinterpret_cast<const uint2*>(r2 + 128 + lane4);
        uint2 q3 = *reinterpret_cast<const uint2*>(r3 + lane4);
        uint2 v3 = *reinterpret_cast<const uint2*>(r3 + 128 + lane4);
        gate4(a0, kk, q0, v0);
        gate4(a1, kk, q1, v1);
        gate4(a0, kk, q2, v2);
        gate4(a1, kk, q3, v3);
    }
    for (; j < end; j++) {
        const __half* r = g_qvh + (size_t)g_esrc[j] * 256;
        uint2 q = *reinterpret_cast<const uint2*>(r + lane4);
        uint2 v = *reinterpret_cast<const uint2*>(r + 128 + lane4);
        gate4(a0, kk, q, v);
    }

    float4 ss = *reinterpret_cast<const float4*>(ks_row + 128 + lane4);
    float4 r = make_float4(fmaxf(a0.x + a1.x + ss.x, 0.f),
                           fmaxf(a0.y + a1.y + ss.y, 0.f),
                           fmaxf(a0.z + a1.z + ss.z, 0.f),
                           fmaxf(a0.w + a1.w + ss.w, 0.f));
    size_t fo = (size_t)gw * DF + lane4;
    if (split_out) {
        __nv_bfloat16 h0 = __float2bfloat16(r.x), h1 = __float2bfloat16(r.y);
        __nv_bfloat16 h2 = __float2bfloat16(r.z), h3 = __float2bfloat16(r.w);
        __nv_bfloat16 l0 = __float2bfloat16(r.x - __bfloat162float(h0));
        __nv_bfloat16 l1 = __float2bfloat16(r.y - __bfloat162float(h1));
        __nv_bfloat16 l2 = __float2bfloat16(r.z - __bfloat162float(h2));
        __nv_bfloat16 l3 = __float2bfloat16(r.w - __bfloat162float(h3));
        uint2 ph, pl;
        ph.x = (uint32_t)__bfloat16_as_ushort(h0) | ((uint32_t)__bfloat16_as_ushort(h1) << 16);
        ph.y = (uint32_t)__bfloat16_as_ushort(h2) | ((uint32_t)__bfloat16_as_ushort(h3) << 16);
        pl.x = (uint32_t)__bfloat16_as_ushort(l0) | ((uint32_t)__bfloat16_as_ushort(l1) << 16);
        pl.y = (uint32_t)__bfloat16_as_ushort(l2) | ((uint32_t)__bfloat16_as_ushort(l3) << 16);
        *reinterpret_cast<uint2*>(g_ahi + fo) = ph;
        *reinterpret_cast<uint2*>(g_alo + fo) = pl;
    } else {
        *reinterpret_cast<float4*>(g_h1 + fo) = r;
    }
}

// ---------------- layer 3 (D_OUT = 1) ----------------
__global__ void gemm3_kernel(const float* __restrict__ Wk, const float* __restrict__ Wq,
                             const float* __restrict__ Wv, const float* __restrict__ Ws,
                             const float* __restrict__ bias) {
    int gw = (blockIdx.x * blockDim.x + threadIdx.x) >> 5;
    if (gw >= N_NODES) return;
    int lane = threadIdx.x & 31;
    float4 x4 = *reinterpret_cast<const float4*>(g_h1 + (size_t)gw * DF + lane * 4);
    float4 wk = *reinterpret_cast<const float4*>(Wk + lane * 4);
    float4 wq = *reinterpret_cast<const float4*>(Wq + lane * 4);
    float4 wv = *reinterpret_cast<const float4*>(Wv + lane * 4);
    float4 ws = *reinterpret_cast<const float4*>(Ws + lane * 4);
    float pk = x4.x * wk.x + x4.y * wk.y + x4.z * wk.z + x4.w * wk.w;
    float pq = x4.x * wq.x + x4.y * wq.y + x4.z * wq.z + x4.w * wq.w;
    float pv = x4.x * wv.x + x4.y * wv.y + x4.z * wv.z + x4.w * wv.w;
    float ps = x4.x * ws.x + x4.y * ws.y + x4.z * ws.z + x4.w * ws.w;
#pragma unroll
    for (int o = 16; o; o >>= 1) {
        pk += __shfl_xor_sync(0xffffffffu, pk, o);
        pq += __shfl_xor_sync(0xffffffffu, pq, o);
        pv += __shfl_xor_sync(0xffffffffu, pv, o);
        ps += __shfl_xor_sync(0xffffffffu, ps, o);
    }
    if (lane == 0) {
        g3k[gw] = pk; g3q[gw] = pq; g3v[gw] = pv; g3s[gw] = ps + bias[0];
    }
}

__global__ void agg3_kernel(float* __restrict__ out) {
    int i = blockIdx.x * blockDim.x + threadIdx.x;
    if (i >= N_NODES) return;
    float ki = g3k[i];
    float acc = 0.f;
    int end = g_rowptr[i + 1];
    for (int j = g_rowptr[i]; j < end; j++) {
        int s = g_esrc[j];
        acc += fsig(ki + g3q[s]) * g3v[s];
    }
    out[i] = acc + g3s[i];
}

// ---------------- launch ----------------
extern "C" void kernel_launch(void* const* d_in, const int* in_sizes, int n_in,
                              void* d_out, int out_size) {
    const float* x   = (const float*)d_in[0];
    const int*   ei  = (const int*)d_in[1];
    const int*   src = ei;
    const int*   dst = ei + N_EDGES;
    const float* Wk1 = (const float*)d_in[2];
    const float* Wq1 = (const float*)d_in[3];
    const float* Wv1 = (const float*)d_in[4];
    const float* Ws1 = (const float*)d_in[5];
    const float* b1  = (const float*)d_in[6];
    const float* Wk2 = (const float*)d_in[7];
    const float* Wq2 = (const float*)d_in[8];
    const float* Wv2 = (const float*)d_in[9];
    const float* Ws2 = (const float*)d_in[10];
    const float* b2  = (const float*)d_in[11];
    const float* Wk3 = (const float*)d_in[12];
    const float* Wq3 = (const float*)d_in[13];
    const float* Wv3 = (const float*)d_in[14];
    const float* Ws3 = (const float*)d_in[15];
    const float* b3  = (const float*)d_in[16];
    float* out = (float*)d_out;

    cudaFuncSetAttribute(mma_kernel, cudaFuncAttributeMaxDynamicSharedMemorySize, SM_TOTAL);

    // CSR build (reused by all 3 layers)
    zero_cnt_kernel<<<(N_NODES + 255) / 256, 256>>>();
    hist_kernel<<<(N_EDGES + 255) / 256, 256>>>(dst);
    scan_kernel<<<1, 1024>>>();
    scatter_kernel<<<(N_EDGES + 255) / 256, 256>>>(src, dst);

    dim3 mgrid(NTILES, 4);
    int  conv_blocks = ((N_NODES * DF) / 4 + 255) / 256;
    int  agg_blocks  = (N_NODES * 32 + 255) / 256;

    // layer 1
    convw_kernel<<<256, 256>>>(Wk1, Wq1, Wv1, Ws1);
    convx_kernel<<<conv_blocks, 256>>>(x);
    mma_kernel<<<mgrid, 256, SM_TOTAL>>>(b1);
    agg_kernel<<<agg_blocks, 256>>>(1);       // writes bf16 hi/lo for layer 2
    // layer 2
    convw_kernel<<<256, 256>>>(Wk2, Wq2, Wv2, Ws2);
    mma_kernel<<<mgrid, 256, SM_TOTAL>>>(b2);
    agg_kernel<<<agg_blocks, 256>>>(0);       // writes fp32 h1 for layer 3
    // layer 3
    gemm3_kernel<<<agg_blocks, 256>>>(Wk3, Wq3, Wv3, Ws3, b3);
    agg3_kernel<<<(N_NODES + 255) / 256, 256>>>(out);
}

// round 10
// speedup vs baseline: 2.1861x; 1.0654x over previous
#include <cuda_runtime.h>
#include <cuda_bf16.h>
#include <cuda_fp16.h>
#include <cstdint>

#define N_NODES 100000
#define N_EDGES 1600000
#define DF      128
#define NTILES  782          // ceil(100000/128)

// ---------------- scratch (device globals: allocation-free) ----------------
// per-src row (fp16): [q(128) | v(128)]  -> 512B/node, 51MB total (L2-resident)
static __device__ __half g_qvh[(size_t)N_NODES * 256];
// per-dst row (fp32): [k(128) | s(128)]
static __device__ float g_ks[(size_t)N_NODES * 256];
static __device__ int   g_rowptr[N_NODES + 1];
static __device__ int   g_fill[N_NODES];
static __device__ int   g_esrc[N_EDGES];
// bf16 hi/lo split operands
static __device__ __nv_bfloat16 g_ahi[(size_t)N_NODES * DF];
static __device__ __nv_bfloat16 g_alo[(size_t)N_NODES * DF];
static __device__ __nv_bfloat16 g_bthi[4 * 128 * 128];   // transposed [mat][n][k]
static __device__ __nv_bfloat16 g_btlo[4 * 128 * 128];
// layer-3 scalars
static __device__ float g3k[N_NODES], g3q[N_NODES], g3v[N_NODES], g3s[N_NODES];

// ---------------- helpers ----------------
__device__ __forceinline__ uint32_t smem_u32(const void* p) {
    uint32_t a;
    asm("{ .reg .u64 t; cvta.to.shared.u64 t, %1; cvt.u32.u64 %0, t; }" : "=r"(a) : "l"(p));
    return a;
}

// XOR swizzle: tile is [128 rows][128 bf16] = row stride 256B, 16 chunks of 16B.
__device__ __forceinline__ uint32_t swz(int row, int chunk) {
    return (uint32_t)(row * 256 + ((chunk ^ (row & 7)) << 4));
}

#define LDSM_X4(r0, r1, r2, r3, addr) \
    asm volatile("ldmatrix.sync.aligned.m8n8.x4.shared.b16 {%0,%1,%2,%3}, [%4];" \
        : "=r"(r0), "=r"(r1), "=r"(r2), "=r"(r3) : "r"(addr))
#define LDSM_X2(r0, r1, addr) \
    asm volatile("ldmatrix.sync.aligned.m8n8.x2.shared.b16 {%0,%1}, [%2];" \
        : "=r"(r0), "=r"(r1) : "r"(addr))
#define MMA16816(d, a, b) \
    asm volatile("mma.sync.aligned.m16n8k16.row.col.f32.bf16.bf16.f32 " \
        "{%0,%1,%2,%3},{%4,%5,%6,%7},{%8,%9},{%0,%1,%2,%3};" \
        : "+f"((d)[0]), "+f"((d)[1]), "+f"((d)[2]), "+f"((d)[3]) \
        : "r"((a)[0]), "r"((a)[1]), "r"((a)[2]), "r"((a)[3]), "r"((b)[0]), "r"((b)[1]))

// exact sigmoid (2 MUFU: EX2 + RCP) — used in final layer only
__device__ __forceinline__ float fsig(float x) {
    return __fdividef(1.f, 1.f + __expf(-x));
}
// fast sigmoid (1 MUFU): sigma(x) = 0.5*tanh(x/2) + 0.5
__device__ __forceinline__ float fsig_t(float x) {
    float t;
    asm("tanh.approx.f32 %0, %1;" : "=f"(t) : "f"(x * 0.5f));
    return fmaf(t, 0.5f, 0.5f);
}

// ---------------- CSR build ----------------
__global__ void zero_cnt_kernel() {
    int i = blockIdx.x * blockDim.x + threadIdx.x;
    if (i < N_NODES) g_fill[i] = 0;
}
__global__ void hist_kernel(const int* __restrict__ dst) {
    int e = blockIdx.x * blockDim.x + threadIdx.x;
    if (e < N_EDGES) atomicAdd(&g_fill[dst[e]], 1);
}
__global__ void scan_kernel() {
    __shared__ int wsum[32];
    __shared__ int carry;
    int tid = threadIdx.x, lane = tid & 31, wid = tid >> 5;
    if (tid == 0) carry = 0;
    __syncthreads();
    for (int base = 0; base < N_NODES; base += 4096) {
        int idx = base + tid * 4;
        int v0 = 0, v1 = 0, v2 = 0, v3 = 0;
        if (idx + 3 < N_NODES) {
            int4 t = *reinterpret_cast<const int4*>(g_fill + idx);
            v0 = t.x; v1 = t.y; v2 = t.z; v3 = t.w;
        } else {
            if (idx + 0 < N_NODES) v0 = g_fill[idx + 0];
            if (idx + 1 < N_NODES) v1 = g_fill[idx + 1];
            if (idx + 2 < N_NODES) v2 = g_fill[idx + 2];
            if (idx + 3 < N_NODES) v3 = g_fill[idx + 3];
        }
        int s0 = v0, s1 = s0 + v1, s2 = s1 + v2, s3 = s2 + v3;
        int x = s3;
#pragma unroll
        for (int o = 1; o < 32; o <<= 1) { int t = __shfl_up_sync(~0u, x, o); if (lane >= o) x += t; }
        if (lane == 31) wsum[wid] = x;
        __syncthreads();
        if (wid == 0) {
            int y = wsum[lane];
#pragma unroll
            for (int o = 1; o < 32; o <<= 1) { int t = __shfl_up_sync(~0u, y, o); if (lane >= o) y += t; }
            wsum[lane] = y;
        }
        __syncthreads();
        int excl = carry + (x - s3) + (wid ? wsum[wid - 1] : 0);
        int e0 = excl, e1 = excl + s0, e2 = excl + s1, e3 = excl + s2;
        if (idx + 0 < N_NODES) { g_rowptr[idx + 0] = e0; g_fill[idx + 0] = e0; }
        if (idx + 1 < N_NODES) { g_rowptr[idx + 1] = e1; g_fill[idx + 1] = e1; }
        if (idx + 2 < N_NODES) { g_rowptr[idx + 2] = e2; g_fill[idx + 2] = e2; }
        if (idx + 3 < N_NODES) { g_rowptr[idx + 3] = e3; g_fill[idx + 3] = e3; }
        __syncthreads();
        if (tid == 0) carry += wsum[31];
        __syncthreads();
    }
    if (tid == 0) g_rowptr[N_NODES] = N_EDGES;
}
__global__ void scatter_kernel(const int* __restrict__ src, const int* __restrict__ dst) {
    int e = blockIdx.x * blockDim.x + threadIdx.x;
    if (e < N_EDGES) {
        int d = dst[e];
        int p = atomicAdd(&g_fill[d], 1);
        g_esrc[p] = src[e];
    }
}

// ---------------- fp32 -> bf16 hi/lo conversion (layer-1 input only) ----------
__global__ void convx_kernel(const float* __restrict__ X) {
    int i = blockIdx.x * blockDim.x + threadIdx.x;
    if (i >= (N_NODES * DF) / 4) return;
    float4 v = *reinterpret_cast<const float4*>(X + (size_t)i * 4);
    __nv_bfloat16 h0 = __float2bfloat16(v.x), h1 = __float2bfloat16(v.y);
    __nv_bfloat16 h2 = __float2bfloat16(v.z), h3 = __float2bfloat16(v.w);
    __nv_bfloat16 l0 = __float2bfloat16(v.x - __bfloat162float(h0));
    __nv_bfloat16 l1 = __float2bfloat16(v.y - __bfloat162float(h1));
    __nv_bfloat16 l2 = __float2bfloat16(v.z - __bfloat162float(h2));
    __nv_bfloat16 l3 = __float2bfloat16(v.w - __bfloat162float(h3));
    uint2 ph, pl;
    ph.x = (uint32_t)__bfloat16_as_ushort(h0) | ((uint32_t)__bfloat16_as_ushort(h1) << 16);
    ph.y = (uint32_t)__bfloat16_as_ushort(h2) | ((uint32_t)__bfloat16_as_ushort(h3) << 16);
    pl.x = (uint32_t)__bfloat16_as_ushort(l0) | ((uint32_t)__bfloat16_as_ushort(l1) << 16);
    pl.y = (uint32_t)__bfloat16_as_ushort(l2) | ((uint32_t)__bfloat16_as_ushort(l3) << 16);
    *reinterpret_cast<uint2*>(g_ahi + (size_t)i * 4) = ph;
    *reinterpret_cast<uint2*>(g_alo + (size_t)i * 4) = pl;
}

__global__ void convw_kernel(const float* __restrict__ Wk, const float* __restrict__ Wq,
                             const float* __restrict__ Wv, const float* __restrict__ Ws) {
    int idx = blockIdx.x * blockDim.x + threadIdx.x;
    if (idx >= 4 * 16384) return;
    int m = idx >> 14, rem = idx & 16383, k = rem >> 7, n = rem & 127;
    const float* W = (m == 0) ? Wk : (m == 1) ? Wq : (m == 2) ? Wv : Ws;
    float v = W[k * 128 + n];
    __nv_bfloat16 h = __float2bfloat16(v);
    __nv_bfloat16 l = __float2bfloat16(v - __bfloat162float(h));
    g_bthi[m * 16384 + n * 128 + k] = h;   // transposed [n][k]
    g_btlo[m * 16384 + n * 128 + k] = l;
}

// ---------------- HMMA bf16 hi/lo split GEMM ----------------
// grid = (NTILES, 4): blockIdx.y = which weight matrix (k,q,v,s).
// Outputs: k -> g_ks[:,0:128] fp32, s -> g_ks[:,128:256] fp32,
//          q -> g_qvh[:,0:128] fp16, v -> g_qvh[:,128:256] fp16.
#define SM_AH 0
#define SM_AL 32768
#define SM_BH 65536
#define SM_BL 98304
#define SM_TOTAL 131072

__global__ void __launch_bounds__(256, 1) mma_kernel(const float* __restrict__ bias) {
    extern __shared__ char sm[];
    uint32_t sb = smem_u32(sm);
    const int tid = threadIdx.x, wid = tid >> 5, lane = tid & 31;
    const int mat = blockIdx.y;
    const int row0 = blockIdx.x * 128;

    const __nv_bfloat16* Bh_g = g_bthi + (size_t)mat * 16384;
    const __nv_bfloat16* Bl_g = g_btlo + (size_t)mat * 16384;
#pragma unroll
    for (int p = 0; p < 8; p++) {
        int c = tid + p * 256;            // 0..2047
        int r = c >> 4, ch = c & 15;
        uint32_t so = swz(r, ch);
        int gr = row0 + r;
        uint4 vh = make_uint4(0, 0, 0, 0), vl = make_uint4(0, 0, 0, 0);
        if (gr < N_NODES) {
            vh = *reinterpret_cast<const uint4*>(g_ahi + (size_t)gr * DF + ch * 8);
            vl = *reinterpret_cast<const uint4*>(g_alo + (size_t)gr * DF + ch * 8);
        }
        *reinterpret_cast<uint4*>(sm + SM_AH + so) = vh;
        *reinterpret_cast<uint4*>(sm + SM_AL + so) = vl;
        *reinterpret_cast<uint4*>(sm + SM_BH + so) =
            *reinterpret_cast<const uint4*>(Bh_g + (size_t)r * 128 + ch * 8);
        *reinterpret_cast<uint4*>(sm + SM_BL + so) =
            *reinterpret_cast<const uint4*>(Bl_g + (size_t)r * 128 + ch * 8);
    }
    __syncthreads();

    const int wm = (wid & 1) * 64;
    const int wn = (wid >> 1) * 32;

    float acc[4][4][4];
#pragma unroll
    for (int i = 0; i < 4; i++)
#pragma unroll
        for (int j = 0; j < 4; j++)
#pragma unroll
            for (int e = 0; e < 4; e++) acc[i][j][e] = 0.f;

    const int a_sel = lane >> 3;
    const int a_row = (lane & 7) + (a_sel & 1) * 8;
    const int a_chk = a_sel >> 1;
    const int b_l   = lane & 15;
    const int b_row = b_l & 7;
    const int b_chk = b_l >> 3;

#pragma unroll
    for (int pass = 0; pass < 3; pass++) {
        uint32_t abase = sb + ((pass == 1) ? SM_AL : SM_AH);
        uint32_t bbase = sb + ((pass == 2) ? SM_BL : SM_BH);
#pragma unroll
        for (int k0 = 0; k0 < 128; k0 += 16) {
            int kc = k0 >> 3;
            uint32_t a[4][4], b[4][2];
#pragma unroll
            for (int mt = 0; mt < 4; mt++) {
                int row = wm + mt * 16 + a_row;
                LDSM_X4(a[mt][0], a[mt][1], a[mt][2], a[mt][3], abase + swz(row, kc + a_chk));
            }
#pragma unroll
            for (int nt = 0; nt < 4; nt++) {
                int row = wn + nt * 8 + b_row;
                LDSM_X2(b[nt][0], b[nt][1], bbase + swz(row, kc + b_chk));
            }
#pragma unroll
            for (int mt = 0; mt < 4; mt++)
#pragma unroll
                for (int nt = 0; nt < 4; nt++)
                    MMA16816(acc[mt][nt], a[mt], b[nt]);
        }
    }

    // epilogue
    const int gq = lane >> 2, tq = lane & 3;
    const bool is_qv = (mat == 1) || (mat == 2);
    float* OutF = (mat == 0) ? g_ks : (g_ks + 128);             // k or s
    __half* OutH = (mat == 1) ? g_qvh : (g_qvh + 128);          // q or v
#pragma unroll
    for (int mt = 0; mt < 4; mt++) {
#pragma unroll
        for (int nt = 0; nt < 4; nt++) {
            int col = wn + nt * 8 + tq * 2;
            float bx = 0.f, by = 0.f;
            if (mat == 3) { bx = bias[col]; by = bias[col + 1]; }
            int r0 = row0 + wm + mt * 16 + gq;
            if (is_qv) {
                if (r0 < N_NODES) {
                    __half2 h = __floats2half2_rn(acc[mt][nt][0], acc[mt][nt][1]);
                    *reinterpret_cast<__half2*>(OutH + (size_t)r0 * 256 + col) = h;
                }
                if (r0 + 8 < N_NODES) {
                    __half2 h = __floats2half2_rn(acc[mt][nt][2], acc[mt][nt][3]);
                    *reinterpret_cast<__half2*>(OutH + (size_t)(r0 + 8) * 256 + col) = h;
                }
            } else {
                if (r0 < N_NODES) {
                    float2 v = make_float2(acc[mt][nt][0] + bx, acc[mt][nt][1] + by);
                    *reinterpret_cast<float2*>(OutF + (size_t)r0 * 256 + col) = v;
                }
                if (r0 + 8 < N_NODES) {
                    float2 v = make_float2(acc[mt][nt][2] + bx, acc[mt][nt][3] + by);
                    *reinterpret_cast<float2*>(OutF + (size_t)(r0 + 8) * 256 + col) = v;
                }
            }
        }
    }
}

// ---------------- edge aggregation: one warp per destination node ----------------
// fp16 q|v rows (L2-resident), tanh-based sigmoid (1 MUFU), unroll-4 for MLP.
// split_out=1: write bf16 hi/lo A operand for next layer's GEMM.
// split_out=0: FUSED layer-3 projections — dot the relu'd h1 vector with the
//              four [128] weight columns in-warp and write g3{k,q,v,s}.
__device__ __forceinline__ void gate4(float4& acc, const float4 kk, uint2 qraw, uint2 vraw) {
    float2 q01 = __half22float2(*reinterpret_cast<__half2*>(&qraw.x));
    float2 q23 = __half22float2(*reinterpret_cast<__half2*>(&qraw.y));
    float2 v01 = __half22float2(*reinterpret_cast<__half2*>(&vraw.x));
    float2 v23 = __half22float2(*reinterpret_cast<__half2*>(&vraw.y));
    acc.x = fmaf(fsig_t(kk.x + q01.x), v01.x, acc.x);
    acc.y = fmaf(fsig_t(kk.y + q01.y), v01.y, acc.y);
    acc.z = fmaf(fsig_t(kk.z + q23.x), v23.x, acc.z);
    acc.w = fmaf(fsig_t(kk.w + q23.y), v23.y, acc.w);
}

__global__ void __launch_bounds__(256) agg_kernel(int split_out,
        const float* __restrict__ Wk3, const float* __restrict__ Wq3,
        const float* __restrict__ Wv3, const float* __restrict__ Ws3,
        const float* __restrict__ b3) {
    int gw = (blockIdx.x * blockDim.x + threadIdx.x) >> 5;
    if (gw >= N_NODES) return;
    int lane = threadIdx.x & 31;
    int lane4 = lane * 4;

    const float* ks_row = g_ks + (size_t)gw * 256;
    float4 kk = *reinterpret_cast<const float4*>(ks_row + lane4);
    float4 a0 = make_float4(0.f, 0.f, 0.f, 0.f);
    float4 a1 = make_float4(0.f, 0.f, 0.f, 0.f);

    int j = g_rowptr[gw], end = g_rowptr[gw + 1];
    for (; j + 4 <= end; j += 4) {
        int s0 = g_esrc[j], s1 = g_esrc[j + 1], s2 = g_esrc[j + 2], s3 = g_esrc[j + 3];
        const __half* r0 = g_qvh + (size_t)s0 * 256;
        const __half* r1 = g_qvh + (size_t)s1 * 256;
        const __half* r2 = g_qvh + (size_t)s2 * 256;
        const __half* r3 = g_qvh + (size_t)s3 * 256;
        uint2 q0 = *reinterpret_cast<const uint2*>(r0 + lane4);
        uint2 v0 = *reinterpret_cast<const uint2*>(r0 + 128 + lane4);
        uint2 q1 = *reinterpret_cast<const uint2*>(r1 + lane4);
        uint2 v1 = *reinterpret_cast<const uint2*>(r1 + 128 + lane4);
        uint2 q2 = *reinterpret_cast<const uint2*>(r2 + lane4);
        uint2 v2 = *reinterpret_cast<const uint2*>(r2 + 128 + lane4);
        uint2 q3 = *reinterpret_cast<const uint2*>(r3 + lane4);
        uint2 v3 = *reinterpret_cast<const uint2*>(r3 + 128 + lane4);
        gate4(a0, kk, q0, v0);
        gate4(a1, kk, q1, v1);
        gate4(a0, kk, q2, v2);
        gate4(a1, kk, q3, v3);
    }
    for (; j < end; j++) {
        const __half* r = g_qvh + (size_t)g_esrc[j] * 256;
        uint2 q = *reinterpret_cast<const uint2*>(r + lane4);
        uint2 v = *reinterpret_cast<const uint2*>(r + 128 + lane4);
        gate4(a0, kk, q, v);
    }

    float4 ss = *reinterpret_cast<const float4*>(ks_row + 128 + lane4);
    float4 r = make_float4(fmaxf(a0.x + a1.x + ss.x, 0.f),
                           fmaxf(a0.y + a1.y + ss.y, 0.f),
                           fmaxf(a0.z + a1.z + ss.z, 0.f),
                           fmaxf(a0.w + a1.w + ss.w, 0.f));
    if (split_out) {
        size_t fo = (size_t)gw * DF + lane4;
        __nv_bfloat16 h0 = __float2bfloat16(r.x), h1 = __float2bfloat16(r.y);
        __nv_bfloat16 h2 = __float2bfloat16(r.z), h3 = __float2bfloat16(r.w);
        __nv_bfloat16 l0 = __float2bfloat16(r.x - __bfloat162float(h0));
        __nv_bfloat16 l1 = __float2bfloat16(r.y - __bfloat162float(h1));
        __nv_bfloat16 l2 = __float2bfloat16(r.z - __bfloat162float(h2));
        __nv_bfloat16 l3 = __float2bfloat16(r.w - __bfloat162float(h3));
        uint2 ph, pl;
        ph.x = (uint32_t)__bfloat16_as_ushort(h0) | ((uint32_t)__bfloat16_as_ushort(h1) << 16);
        ph.y = (uint32_t)__bfloat16_as_ushort(h2) | ((uint32_t)__bfloat16_as_ushort(h3) << 16);
        pl.x = (uint32_t)__bfloat16_as_ushort(l0) | ((uint32_t)__bfloat16_as_ushort(l1) << 16);
        pl.y = (uint32_t)__bfloat16_as_ushort(l2) | ((uint32_t)__bfloat16_as_ushort(l3) << 16);
        *reinterpret_cast<uint2*>(g_ahi + fo) = ph;
        *reinterpret_cast<uint2*>(g_alo + fo) = pl;
    } else {
        // fused layer-3 projections (D_OUT = 1)
        float4 wk = *reinterpret_cast<const float4*>(Wk3 + lane4);
        float4 wq = *reinterpret_cast<const float4*>(Wq3 + lane4);
        float4 wv = *reinterpret_cast<const float4*>(Wv3 + lane4);
        float4 ws = *reinterpret_cast<const float4*>(Ws3 + lane4);
        float pk = r.x * wk.x + r.y * wk.y + r.z * wk.z + r.w * wk.w;
        float pq = r.x * wq.x + r.y * wq.y + r.z * wq.z + r.w * wq.w;
        float pv = r.x * wv.x + r.y * wv.y + r.z * wv.z + r.w * wv.w;
        float ps = r.x * ws.x + r.y * ws.y + r.z * ws.z + r.w * ws.w;
#pragma unroll
        for (int o = 16; o; o >>= 1) {
            pk += __shfl_xor_sync(0xffffffffu, pk, o);
            pq += __shfl_xor_sync(0xffffffffu, pq, o);
            pv += __shfl_xor_sync(0xffffffffu, pv, o);
            ps += __shfl_xor_sync(0xffffffffu, ps, o);
        }
        if (lane == 0) {
            g3k[gw] = pk; g3q[gw] = pq; g3v[gw] = pv; g3s[gw] = ps + b3[0];
        }
    }
}

// ---------------- layer 3 edge aggregation (exact sigmoid) ----------------
__global__ void agg3_kernel(float* __restrict__ out) {
    int i = blockIdx.x * blockDim.x + threadIdx.x;
    if (i >= N_NODES) return;
    float ki = g3k[i];
    float acc = 0.f;
    int end = g_rowptr[i + 1];
    for (int j = g_rowptr[i]; j < end; j++) {
        int s = g_esrc[j];
        acc += fsig(ki + g3q[s]) * g3v[s];
    }
    out[i] = acc + g3s[i];
}

// ---------------- launch ----------------
extern "C" void kernel_launch(void* const* d_in, const int* in_sizes, int n_in,
                              void* d_out, int out_size) {
    const float* x   = (const float*)d_in[0];
    const int*   ei  = (const int*)d_in[1];
    const int*   src = ei;
    const int*   dst = ei + N_EDGES;
    const float* Wk1 = (const float*)d_in[2];
    const float* Wq1 = (const float*)d_in[3];
    const float* Wv1 = (const float*)d_in[4];
    const float* Ws1 = (const float*)d_in[5];
    const float* b1  = (const float*)d_in[6];
    const float* Wk2 = (const float*)d_in[7];
    const float* Wq2 = (const float*)d_in[8];
    const float* Wv2 = (const float*)d_in[9];
    const float* Ws2 = (const float*)d_in[10];
    const float* b2  = (const float*)d_in[11];
    const float* Wk3 = (const float*)d_in[12];
    const float* Wq3 = (const float*)d_in[13];
    const float* Wv3 = (const float*)d_in[14];
    const float* Ws3 = (const float*)d_in[15];
    const float* b3  = (const float*)d_in[16];
    float* out = (float*)d_out;

    cudaFuncSetAttribute(mma_kernel, cudaFuncAttributeMaxDynamicSharedMemorySize, SM_TOTAL);

    // CSR build (reused by all 3 layers)
    zero_cnt_kernel<<<(N_NODES + 255) / 256, 256>>>();
    hist_kernel<<<(N_EDGES + 255) / 256, 256>>>(dst);
    scan_kernel<<<1, 1024>>>();
    scatter_kernel<<<(N_EDGES + 255) / 256, 256>>>(src, dst);

    dim3 mgrid(NTILES, 4);
    int  conv_blocks = ((N_NODES * DF) / 4 + 255) / 256;
    int  agg_blocks  = (N_NODES * 32 + 255) / 256;

    // layer 1
    convw_kernel<<<256, 256>>>(Wk1, Wq1, Wv1, Ws1);
    convx_kernel<<<conv_blocks, 256>>>(x);
    mma_kernel<<<mgrid, 256, SM_TOTAL>>>(b1);
    agg_kernel<<<agg_blocks, 256>>>(1, nullptr, nullptr, nullptr, nullptr, nullptr);
    // layer 2 (+fused layer-3 projections in the agg epilogue)
    convw_kernel<<<256, 256>>>(Wk2, Wq2, Wv2, Ws2);
    mma_kernel<<<mgrid, 256, SM_TOTAL>>>(b2);
    agg_kernel<<<agg_blocks, 256>>>(0, Wk3, Wq3, Wv3, Ws3, b3);
    // layer 3 edge aggregation
    agg3_kernel<<<(N_NODES + 255) / 256, 256>>>(out);
}